// round 1
// baseline (speedup 1.0000x reference)
#include <cuda_runtime.h>
#include <math.h>

// ---------------- problem constants ----------------
#define B 32
#define S 512
#define H 512
#define NH 8
#define DH 64
#define INNER 2048
#define BS (B*S)            // 16384
#define BSH ((size_t)B*S*H) // 8388608

// ---------------- scratch (device globals; no runtime alloc allowed) -------
__device__ float g_Q  [BSH];
__device__ float g_K  [BSH];
__device__ float g_V  [BSH];
__device__ float g_KKH[BSH];   // first bhk projection, then K + 0.5*(bhk+pk)
__device__ float g_QH [BSH];   // first bhq projection, then 0.5*(bhq+pq)
__device__ float g_PK [S*H];
__device__ float g_PQ [S*H];
__device__ float g_SC [(size_t)B*NH*S*S];  // scores / probs (268MB)
__device__ float g_CTX[BSH];
__device__ float g_ATT[BSH];   // pre-LN buffers (reused)
__device__ float g_AO [BSH];   // attn_out (post LN1)
__device__ float g_H1 [(size_t)BS*INNER];

// ---------------- generic SGEMM: C = A[MxK] @ W[KxN] + bias (+epilogue) ----
// EPI: 0 = bias, 1 = bias + residual R, 2 = bias + exact GELU
#define GBM 128
#define GBN 128
#define GBK 16

template<int EPI>
__global__ __launch_bounds__(256)
void gemm_kernel(const float* __restrict__ A, const float* __restrict__ W,
                 const float* __restrict__ bias, const float* __restrict__ R,
                 float* __restrict__ C, int M, int N, int K)
{
    __shared__ float As[GBK][GBM + 4];   // A stored transposed (k-major)
    __shared__ float Bs[GBK][GBN];

    const int tid = threadIdx.x;
    const int m0 = blockIdx.y * GBM;
    const int n0 = blockIdx.x * GBN;

    const int ty = (tid >> 4) * 8;    // 0..120
    const int tx = (tid & 15) * 8;    // 0..120

    float acc[8][8];
    #pragma unroll
    for (int i = 0; i < 8; i++)
        #pragma unroll
        for (int j = 0; j < 8; j++) acc[i][j] = 0.0f;

    for (int k0 = 0; k0 < K; k0 += GBK) {
        // load A tile: 128 rows x 16 cols -> 512 float4, 2 per thread
        #pragma unroll
        for (int it = 0; it < 2; it++) {
            int f = tid + it * 256;
            int r = f >> 2;            // 0..127
            int c = (f & 3) * 4;       // 0,4,8,12
            float4 a4 = *(const float4*)(A + (size_t)(m0 + r) * K + k0 + c);
            As[c + 0][r] = a4.x; As[c + 1][r] = a4.y;
            As[c + 2][r] = a4.z; As[c + 3][r] = a4.w;
        }
        // load B tile: 16 rows x 128 cols -> 512 float4, 2 per thread
        #pragma unroll
        for (int it = 0; it < 2; it++) {
            int f = tid + it * 256;
            int r = f >> 5;            // 0..15
            int c = (f & 31) * 4;      // 0..124
            *(float4*)&Bs[r][c] = *(const float4*)(W + (size_t)(k0 + r) * N + n0 + c);
        }
        __syncthreads();

        #pragma unroll
        for (int k = 0; k < GBK; k++) {
            float a[8], b[8];
            *(float4*)&a[0] = *(const float4*)&As[k][ty];
            *(float4*)&a[4] = *(const float4*)&As[k][ty + 4];
            *(float4*)&b[0] = *(const float4*)&Bs[k][tx];
            *(float4*)&b[4] = *(const float4*)&Bs[k][tx + 4];
            #pragma unroll
            for (int i = 0; i < 8; i++)
                #pragma unroll
                for (int j = 0; j < 8; j++)
                    acc[i][j] += a[i] * b[j];
        }
        __syncthreads();
    }

    // epilogue
    #pragma unroll
    for (int i = 0; i < 8; i++) {
        int row = m0 + ty + i;
        #pragma unroll
        for (int j = 0; j < 8; j++) {
            int col = n0 + tx + j;
            float v = acc[i][j] + bias[col];
            if (EPI == 1) v += R[(size_t)row * N + col];
            if (EPI == 2) v = 0.5f * v * (1.0f + erff(v * 0.7071067811865475f));
            C[(size_t)row * N + col] = v;
        }
    }
}

// ---------------- elementwise combine: fold pos/beha into K-hat, Q-hat -----
__global__ void combine_kernel()
{
    int i = blockIdx.x * blockDim.x + threadIdx.x;   // float4 index
    // element e = i*4; col4 = i%128; s = (i/128)%512
    int col4 = i & 127;
    int s = (i >> 7) & 511;
    float4 kk = ((const float4*)g_K)[i];
    float4 kh = ((const float4*)g_KKH)[i];
    float4 pk = ((const float4*)g_PK)[s * 128 + col4];
    float4 qh = ((const float4*)g_QH)[i];
    float4 pq = ((const float4*)g_PQ)[s * 128 + col4];
    float4 o1, o2;
    o1.x = kk.x + 0.5f * (kh.x + pk.x);
    o1.y = kk.y + 0.5f * (kh.y + pk.y);
    o1.z = kk.z + 0.5f * (kh.z + pk.z);
    o1.w = kk.w + 0.5f * (kh.w + pk.w);
    o2.x = 0.5f * (qh.x + pq.x);
    o2.y = 0.5f * (qh.y + pq.y);
    o2.z = 0.5f * (qh.z + pq.z);
    o2.w = 0.5f * (qh.w + pq.w);
    ((float4*)g_KKH)[i] = o1;
    ((float4*)g_QH)[i]  = o2;
}

// ---------------- attention scores: S = (Q·KKHt + QH·Kt)/8 + mask ----------
// grid (S/64, S/64, B*NH), 256 threads, 4x4 per thread
__global__ __launch_bounds__(256)
void scores_kernel(const int* __restrict__ iseq)
{
    __shared__ float Qs [64][36];
    __shared__ float QHs[64][36];
    __shared__ float Ks [64][36];
    __shared__ float KKs[64][36];
    __shared__ float maskadd[64];

    const int b = blockIdx.z >> 3;
    const int h = blockIdx.z & 7;
    const int q0 = blockIdx.y * 64;
    const int c0 = blockIdx.x * 64;
    const int tid = threadIdx.x;

    if (tid < 64) {
        int kcol = c0 + tid;
        maskadd[tid] = (iseq[b * S + kcol] > 0) ? 0.0f : -10000.0f;
    }

    const int ty = (tid >> 4) * 4;
    const int tx = (tid & 15) * 4;

    float acc[4][4];
    #pragma unroll
    for (int i = 0; i < 4; i++)
        #pragma unroll
        for (int j = 0; j < 4; j++) acc[i][j] = 0.0f;

    const size_t baseQ = ((size_t)b * S + q0) * H + h * DH;
    const size_t baseK = ((size_t)b * S + c0) * H + h * DH;

    for (int kk = 0; kk < DH; kk += 32) {
        #pragma unroll
        for (int it = 0; it < 2; it++) {
            int f = tid + it * 256;
            int r = f >> 3;
            int c = (f & 7) * 4;
            *(float4*)&Qs [r][c] = *(const float4*)(g_Q   + baseQ + (size_t)r * H + kk + c);
            *(float4*)&QHs[r][c] = *(const float4*)(g_QH  + baseQ + (size_t)r * H + kk + c);
            *(float4*)&Ks [r][c] = *(const float4*)(g_K   + baseK + (size_t)r * H + kk + c);
            *(float4*)&KKs[r][c] = *(const float4*)(g_KKH + baseK + (size_t)r * H + kk + c);
        }
        __syncthreads();
        #pragma unroll
        for (int k = 0; k < 32; k++) {
            float a0[4], a1[4];
            #pragma unroll
            for (int i = 0; i < 4; i++) { a0[i] = Qs[ty + i][k]; a1[i] = QHs[ty + i][k]; }
            #pragma unroll
            for (int j = 0; j < 4; j++) {
                float b0 = KKs[tx + j][k];
                float b1 = Ks [tx + j][k];
                #pragma unroll
                for (int i = 0; i < 4; i++)
                    acc[i][j] += a0[i] * b0 + a1[i] * b1;
            }
        }
        __syncthreads();
    }

    float* out = g_SC + (((size_t)(b * NH + h) * S + q0) * S) + c0;
    #pragma unroll
    for (int i = 0; i < 4; i++) {
        int qr = ty + i;
        #pragma unroll
        for (int j = 0; j < 4; j++) {
            int kc = tx + j;
            float madd = ((c0 + kc) <= (q0 + qr)) ? maskadd[kc] : -10000.0f;
            out[(size_t)qr * S + kc] = acc[i][j] * 0.125f + madd;
        }
    }
}

// ---------------- softmax over last dim (512), in place ----------
__global__ __launch_bounds__(256)
void softmax_kernel()
{
    size_t row = blockIdx.x;
    float* p = g_SC + row * S;
    int t = threadIdx.x;
    float v0 = p[t], v1 = p[t + 256];

    __shared__ float red[8];
    __shared__ float bc;

    float m = fmaxf(v0, v1);
    #pragma unroll
    for (int o = 16; o; o >>= 1) m = fmaxf(m, __shfl_xor_sync(0xffffffffu, m, o));
    if ((t & 31) == 0) red[t >> 5] = m;
    __syncthreads();
    if (t == 0) {
        float mm = red[0];
        #pragma unroll
        for (int i = 1; i < 8; i++) mm = fmaxf(mm, red[i]);
        bc = mm;
    }
    __syncthreads();
    m = bc;

    float e0 = expf(v0 - m), e1 = expf(v1 - m);
    float s = e0 + e1;
    #pragma unroll
    for (int o = 16; o; o >>= 1) s += __shfl_xor_sync(0xffffffffu, s, o);
    __syncthreads();
    if ((t & 31) == 0) red[t >> 5] = s;
    __syncthreads();
    if (t == 0) {
        float ss = 0.0f;
        #pragma unroll
        for (int i = 0; i < 8; i++) ss += red[i];
        bc = 1.0f / ss;
    }
    __syncthreads();
    float inv = bc;
    p[t] = e0 * inv;
    p[t + 256] = e1 * inv;
}

// ---------------- ctx = probs @ V (per b,h), writes [B,S,H] layout ---------
// grid (S/64, B*NH), 256 threads, 4x4 per thread
__global__ __launch_bounds__(256)
void pv_kernel()
{
    __shared__ float Ps[64][68];
    __shared__ float Vs[64][68];

    const int b = blockIdx.y >> 3;
    const int h = blockIdx.y & 7;
    const int q0 = blockIdx.x * 64;
    const int tid = threadIdx.x;
    const int ty = (tid >> 4) * 4;
    const int tx = (tid & 15) * 4;

    float acc[4][4];
    #pragma unroll
    for (int i = 0; i < 4; i++)
        #pragma unroll
        for (int j = 0; j < 4; j++) acc[i][j] = 0.0f;

    const float* prob = g_SC + ((size_t)(b * NH + h) * S + q0) * S;

    for (int kt = 0; kt < S; kt += 64) {
        #pragma unroll
        for (int it = 0; it < 4; it++) {
            int f = tid + it * 256;
            int r = f >> 4;
            int c = (f & 15) * 4;
            *(float4*)&Ps[r][c] = *(const float4*)(prob + (size_t)r * S + kt + c);
            *(float4*)&Vs[r][c] = *(const float4*)(g_V + ((size_t)b * S + kt + r) * H + h * DH + c);
        }
        __syncthreads();
        #pragma unroll
        for (int k = 0; k < 64; k++) {
            float a[4];
            #pragma unroll
            for (int i = 0; i < 4; i++) a[i] = Ps[ty + i][k];
            float bb[4];
            *(float4*)&bb[0] = *(const float4*)&Vs[k][tx];
            #pragma unroll
            for (int i = 0; i < 4; i++)
                #pragma unroll
                for (int j = 0; j < 4; j++)
                    acc[i][j] += a[i] * bb[j];
        }
        __syncthreads();
    }

    #pragma unroll
    for (int i = 0; i < 4; i++)
        #pragma unroll
        for (int j = 0; j < 4; j++)
            g_CTX[((size_t)b * S + q0 + ty + i) * H + h * DH + tx + j] = acc[i][j];
}

// ---------------- LayerNorm over last dim (512) -----------------
__global__ __launch_bounds__(256)
void ln_kernel(const float* __restrict__ in, const float* __restrict__ gam,
               const float* __restrict__ bet, float* __restrict__ out)
{
    size_t row = blockIdx.x;
    const float* p = in + row * H;
    int t = threadIdx.x;
    float x0 = p[t], x1 = p[t + 256];

    __shared__ float r1[8], r2[8];
    float s = x0 + x1;
    float sq = x0 * x0 + x1 * x1;
    #pragma unroll
    for (int o = 16; o; o >>= 1) {
        s  += __shfl_xor_sync(0xffffffffu, s, o);
        sq += __shfl_xor_sync(0xffffffffu, sq, o);
    }
    if ((t & 31) == 0) { r1[t >> 5] = s; r2[t >> 5] = sq; }
    __syncthreads();
    if (t == 0) {
        float S1 = 0.0f, S2 = 0.0f;
        #pragma unroll
        for (int i = 0; i < 8; i++) { S1 += r1[i]; S2 += r2[i]; }
        r1[0] = S1; r2[0] = S2;
    }
    __syncthreads();
    float mean = r1[0] * (1.0f / (float)H);
    float var  = r2[0] * (1.0f / (float)H) - mean * mean;
    float rstd = rsqrtf(var + 1e-12f);
    out[row * H + t]       = (x0 - mean) * rstd * gam[t]       + bet[t];
    out[row * H + t + 256] = (x1 - mean) * rstd * gam[t + 256] + bet[t + 256];
}

// ---------------- launcher ----------------
extern "C" void kernel_launch(void* const* d_in, const int* in_sizes, int n_in,
                              void* d_out, int out_size)
{
    const float* x    = (const float*)d_in[0];
    const float* vin  = (const float*)d_in[1];
    const float* beha = (const float*)d_in[2];
    const float* pos  = (const float*)d_in[3];
    const float* Wq   = (const float*)d_in[4];
    const float* bq   = (const float*)d_in[5];
    const float* Wk   = (const float*)d_in[6];
    const float* bk   = (const float*)d_in[7];
    const float* Wv   = (const float*)d_in[8];
    const float* bv   = (const float*)d_in[9];
    const float* Wpk  = (const float*)d_in[10];
    const float* bpk  = (const float*)d_in[11];
    const float* Wpq  = (const float*)d_in[12];
    const float* bpq  = (const float*)d_in[13];
    const float* Wbk  = (const float*)d_in[14];
    const float* bbk  = (const float*)d_in[15];
    const float* Wbq  = (const float*)d_in[16];
    const float* bbq  = (const float*)d_in[17];
    const float* Wd   = (const float*)d_in[18];
    const float* bd   = (const float*)d_in[19];
    const float* ln_g = (const float*)d_in[20];
    const float* ln_b = (const float*)d_in[21];
    const float* W1   = (const float*)d_in[22];
    const float* b1   = (const float*)d_in[23];
    const float* W2   = (const float*)d_in[24];
    const float* b2   = (const float*)d_in[25];
    const float* ln2g = (const float*)d_in[26];
    const float* ln2b = (const float*)d_in[27];
    const int*   iseq = (const int*)d_in[28];
    float* out = (float*)d_out;

    float *pQ, *pK, *pV, *pKKH, *pQH, *pPK, *pPQ, *pCTX, *pATT, *pAO, *pH1;
    cudaGetSymbolAddress((void**)&pQ,   g_Q);
    cudaGetSymbolAddress((void**)&pK,   g_K);
    cudaGetSymbolAddress((void**)&pV,   g_V);
    cudaGetSymbolAddress((void**)&pKKH, g_KKH);
    cudaGetSymbolAddress((void**)&pQH,  g_QH);
    cudaGetSymbolAddress((void**)&pPK,  g_PK);
    cudaGetSymbolAddress((void**)&pPQ,  g_PQ);
    cudaGetSymbolAddress((void**)&pCTX, g_CTX);
    cudaGetSymbolAddress((void**)&pATT, g_ATT);
    cudaGetSymbolAddress((void**)&pAO,  g_AO);
    cudaGetSymbolAddress((void**)&pH1,  g_H1);

    dim3 blk(256);

    // pos projections: [512,512] @ [512,512]
    dim3 gPos(H / GBN, S / GBM);
    gemm_kernel<0><<<gPos, blk>>>(pos, Wpk, bpk, nullptr, pPK, S, H, H);
    gemm_kernel<0><<<gPos, blk>>>(pos, Wpq, bpq, nullptr, pPQ, S, H, H);

    // main projections: [16384,512] @ [512,512]
    dim3 gProj(H / GBN, BS / GBM);
    gemm_kernel<0><<<gProj, blk>>>(x,    Wq,  bq,  nullptr, pQ,   BS, H, H);
    gemm_kernel<0><<<gProj, blk>>>(x,    Wk,  bk,  nullptr, pK,   BS, H, H);
    gemm_kernel<1><<<gProj, blk>>>(vin,  Wv,  bv,  vin,     pV,   BS, H, H);
    gemm_kernel<0><<<gProj, blk>>>(beha, Wbk, bbk, nullptr, pKKH, BS, H, H);
    gemm_kernel<0><<<gProj, blk>>>(beha, Wbq, bbq, nullptr, pQH,  BS, H, H);

    // combine: KKH = K + 0.5*(bhk+pk) ; QH = 0.5*(bhq+pq)
    combine_kernel<<<(BSH / 4) / 256, blk>>>();

    // scores + mask
    scores_kernel<<<dim3(S / 64, S / 64, B * NH), blk>>>(iseq);

    // softmax
    softmax_kernel<<<(unsigned)((size_t)B * NH * S), blk>>>();

    // ctx = probs @ V
    pv_kernel<<<dim3(S / 64, B * NH), blk>>>();

    // output projection + residual x
    gemm_kernel<1><<<gProj, blk>>>(pCTX, Wd, bd, x, pATT, BS, H, H);
    ln_kernel<<<BS, blk>>>(pATT, ln_g, ln_b, pAO);

    // FFN
    dim3 gF1(INNER / GBN, BS / GBM);
    gemm_kernel<2><<<gF1, blk>>>(pAO, W1, b1, nullptr, pH1, BS, INNER, H);
    dim3 gF2(H / GBN, BS / GBM);
    gemm_kernel<1><<<gF2, blk>>>(pH1, W2, b2, pAO, pATT, BS, H, INNER);
    ln_kernel<<<BS, blk>>>(pATT, ln2g, ln2b, out);
}

// round 3
// speedup vs baseline: 2.6728x; 2.6728x over previous
#include <cuda_runtime.h>
#include <math.h>
#include <stdint.h>

// ---------------- problem constants ----------------
#define B 32
#define S 512
#define H 512
#define NH 8
#define DH 64
#define INNER 2048
#define BS (B*S)            // 16384
#define BSH ((size_t)B*S*H) // 8388608

// ---------------- scratch ----------------
__device__ float g_Q  [BSH];
__device__ float g_K  [BSH];
__device__ float g_V  [BSH];
__device__ float g_KKH[BSH];
__device__ float g_QH [BSH];
__device__ float g_PK [S*H];
__device__ float g_PQ [S*H];
__device__ float g_SC [(size_t)B*NH*S*S];
__device__ float g_CTX[BSH];
__device__ float g_ATT[BSH];
__device__ float g_AO [BSH];
__device__ float g_H1 [(size_t)BS*INNER];

// ---------------- helpers ----------------
__device__ __forceinline__ float to_tf32(float x) {
    float r;
    asm("cvt.rna.tf32.f32 %0, %1;" : "=f"(r) : "f"(x));
    return r;
}

__device__ __forceinline__ void mma8(float* c, const uint32_t* a, uint32_t b0, uint32_t b1) {
    asm volatile(
        "mma.sync.aligned.m16n8k8.row.col.f32.tf32.tf32.f32 "
        "{%0,%1,%2,%3}, {%4,%5,%6,%7}, {%8,%9}, {%0,%1,%2,%3};"
        : "+f"(c[0]), "+f"(c[1]), "+f"(c[2]), "+f"(c[3])
        : "r"(a[0]), "r"(a[1]), "r"(a[2]), "r"(a[3]), "r"(b0), "r"(b1));
}

// ================= mma.sync tf32 GEMM =================
// C[M,N] = A[M,K] @ W[K,N] + bias; EPI: 0 bias, 1 +residual, 2 gelu
__global__ __launch_bounds__(256)
void dummy_noop() {}

template<int EPI>
__global__ __launch_bounds__(256)
void mma_gemm(const float* __restrict__ A, const float* __restrict__ W,
              const float* __restrict__ bias, const float* __restrict__ Rres,
              float* __restrict__ C, int M, int N, int K)
{
    __shared__ float As[128][36];   // [m][k], stride 36 (==4 mod 32)
    __shared__ float Bs[32][136];   // [k][n], stride 136 (==8 mod 32)

    const int tid  = threadIdx.x;
    const int lane = tid & 31;
    const int wid  = tid >> 5;
    const int wm   = (wid & 3) * 32;   // warp M offset in tile
    const int wn   = (wid >> 2) * 64;  // warp N offset in tile
    const int m0 = blockIdx.y * 128;
    const int n0 = blockIdx.x * 128;
    const int g  = lane >> 2;   // groupID
    const int tg = lane & 3;    // thread in group

    float acc[2][8][4];
    #pragma unroll
    for (int i = 0; i < 2; i++)
        #pragma unroll
        for (int j = 0; j < 8; j++)
            #pragma unroll
            for (int q = 0; q < 4; q++) acc[i][j][q] = 0.0f;

    float4 stA[4], stB[4];
    const int NC = K >> 5;

    // prologue: load + store chunk 0
    {
        const float* Ag = A + (size_t)m0 * K;
        const float* Bg = W + n0;
        #pragma unroll
        for (int i = 0; i < 4; i++) {
            int f = tid + i * 256;
            stA[i] = *(const float4*)(Ag + (size_t)(f >> 3) * K + (f & 7) * 4);
            stB[i] = *(const float4*)(Bg + (size_t)(f >> 5) * N + (f & 31) * 4);
        }
        #pragma unroll
        for (int i = 0; i < 4; i++) {
            int f = tid + i * 256;
            int ra = f >> 3, ca = (f & 7) * 4;
            As[ra][ca + 0] = to_tf32(stA[i].x); As[ra][ca + 1] = to_tf32(stA[i].y);
            As[ra][ca + 2] = to_tf32(stA[i].z); As[ra][ca + 3] = to_tf32(stA[i].w);
            int rb = f >> 5, cb = (f & 31) * 4;
            Bs[rb][cb + 0] = to_tf32(stB[i].x); Bs[rb][cb + 1] = to_tf32(stB[i].y);
            Bs[rb][cb + 2] = to_tf32(stB[i].z); Bs[rb][cb + 3] = to_tf32(stB[i].w);
        }
    }
    __syncthreads();

    for (int c = 0; c < NC; c++) {
        if (c + 1 < NC) {
            const float* Ag = A + (size_t)m0 * K + (c + 1) * 32;
            const float* Bg = W + (size_t)(c + 1) * 32 * N + n0;
            #pragma unroll
            for (int i = 0; i < 4; i++) {
                int f = tid + i * 256;
                stA[i] = *(const float4*)(Ag + (size_t)(f >> 3) * K + (f & 7) * 4);
                stB[i] = *(const float4*)(Bg + (size_t)(f >> 5) * N + (f & 31) * 4);
            }
        }
        // compute chunk c
        #pragma unroll
        for (int ks = 0; ks < 4; ks++) {
            int k0 = ks * 8;
            uint32_t a[2][4];
            #pragma unroll
            for (int mi = 0; mi < 2; mi++) {
                int row = wm + mi * 16 + g;
                a[mi][0] = __float_as_uint(As[row    ][k0 + tg]);
                a[mi][1] = __float_as_uint(As[row + 8][k0 + tg]);
                a[mi][2] = __float_as_uint(As[row    ][k0 + tg + 4]);
                a[mi][3] = __float_as_uint(As[row + 8][k0 + tg + 4]);
            }
            #pragma unroll
            for (int nj = 0; nj < 8; nj++) {
                int col = wn + nj * 8 + g;
                uint32_t b0 = __float_as_uint(Bs[k0 + tg    ][col]);
                uint32_t b1 = __float_as_uint(Bs[k0 + tg + 4][col]);
                mma8(acc[0][nj], a[0], b0, b1);
                mma8(acc[1][nj], a[1], b0, b1);
            }
        }
        __syncthreads();
        if (c + 1 < NC) {
            #pragma unroll
            for (int i = 0; i < 4; i++) {
                int f = tid + i * 256;
                int ra = f >> 3, ca = (f & 7) * 4;
                As[ra][ca + 0] = to_tf32(stA[i].x); As[ra][ca + 1] = to_tf32(stA[i].y);
                As[ra][ca + 2] = to_tf32(stA[i].z); As[ra][ca + 3] = to_tf32(stA[i].w);
                int rb = f >> 5, cb = (f & 31) * 4;
                Bs[rb][cb + 0] = to_tf32(stB[i].x); Bs[rb][cb + 1] = to_tf32(stB[i].y);
                Bs[rb][cb + 2] = to_tf32(stB[i].z); Bs[rb][cb + 3] = to_tf32(stB[i].w);
            }
            __syncthreads();
        }
    }

    // epilogue
    #pragma unroll
    for (int mi = 0; mi < 2; mi++) {
        #pragma unroll
        for (int nj = 0; nj < 8; nj++) {
            int r0  = m0 + wm + mi * 16 + g;
            int col = n0 + wn + nj * 8 + 2 * tg;
            float b0 = bias[col], b1 = bias[col + 1];
            float v00 = acc[mi][nj][0] + b0, v01 = acc[mi][nj][1] + b1;
            float v10 = acc[mi][nj][2] + b0, v11 = acc[mi][nj][3] + b1;
            if (EPI == 1) {
                v00 += Rres[(size_t)r0 * N + col];
                v01 += Rres[(size_t)r0 * N + col + 1];
                v10 += Rres[(size_t)(r0 + 8) * N + col];
                v11 += Rres[(size_t)(r0 + 8) * N + col + 1];
            }
            if (EPI == 2) {
                v00 = 0.5f * v00 * (1.0f + erff(v00 * 0.7071067811865475f));
                v01 = 0.5f * v01 * (1.0f + erff(v01 * 0.7071067811865475f));
                v10 = 0.5f * v10 * (1.0f + erff(v10 * 0.7071067811865475f));
                v11 = 0.5f * v11 * (1.0f + erff(v11 * 0.7071067811865475f));
            }
            *(float2*)(C + (size_t)r0 * N + col)       = make_float2(v00, v01);
            *(float2*)(C + (size_t)(r0 + 8) * N + col) = make_float2(v10, v11);
        }
    }
}

// ---------------- elementwise combine ----------------
__global__ void combine_kernel()
{
    int i = blockIdx.x * blockDim.x + threadIdx.x;
    int col4 = i & 127;
    int s = (i >> 7) & 511;
    float4 kk = ((const float4*)g_K)[i];
    float4 kh = ((const float4*)g_KKH)[i];
    float4 pk = ((const float4*)g_PK)[s * 128 + col4];
    float4 qh = ((const float4*)g_QH)[i];
    float4 pq = ((const float4*)g_PQ)[s * 128 + col4];
    float4 o1, o2;
    o1.x = kk.x + 0.5f * (kh.x + pk.x);
    o1.y = kk.y + 0.5f * (kh.y + pk.y);
    o1.z = kk.z + 0.5f * (kh.z + pk.z);
    o1.w = kk.w + 0.5f * (kh.w + pk.w);
    o2.x = 0.5f * (qh.x + pq.x);
    o2.y = 0.5f * (qh.y + pq.y);
    o2.z = 0.5f * (qh.z + pq.z);
    o2.w = 0.5f * (qh.w + pq.w);
    ((float4*)g_KKH)[i] = o1;
    ((float4*)g_QH)[i]  = o2;
}

// ---------------- scores: (Q·KKH^T + QH·K^T)/8 + mask, mma.sync ------------
// grid (S/128, S/128, B*NH), 256 threads
#define SC_SMEM ((4*128*36 + 128) * 4)
__global__ __launch_bounds__(256)
void scores_mma(const int* __restrict__ iseq)
{
    extern __shared__ float sm[];
    float (*Qs )[36] = (float(*)[36])(sm);
    float (*QHs)[36] = (float(*)[36])(sm + 4608);
    float (*KKs)[36] = (float(*)[36])(sm + 9216);
    float (*Ks )[36] = (float(*)[36])(sm + 13824);
    float* maskadd   = sm + 18432;

    const int bz = blockIdx.z;
    const int b = bz >> 3;
    const int h = bz & 7;
    const int q0 = blockIdx.y * 128;
    const int c0 = blockIdx.x * 128;
    const int tid = threadIdx.x;
    const int lane = tid & 31;
    const int wid = tid >> 5;
    const int wm = (wid & 3) * 32;
    const int wn = (wid >> 2) * 64;
    const int g = lane >> 2;
    const int tg = lane & 3;

    if (tid < 128)
        maskadd[tid] = (iseq[b * S + c0 + tid] > 0) ? 0.0f : -10000.0f;

    float acc[2][8][4];
    #pragma unroll
    for (int i = 0; i < 2; i++)
        #pragma unroll
        for (int j = 0; j < 8; j++)
            #pragma unroll
            for (int q = 0; q < 4; q++) acc[i][j][q] = 0.0f;

    const size_t baseQ = ((size_t)b * S + q0) * H + h * DH;
    const size_t baseK = ((size_t)b * S + c0) * H + h * DH;

    for (int ck = 0; ck < DH; ck += 32) {
        #pragma unroll
        for (int it = 0; it < 4; it++) {
            int f = tid + it * 256;
            int r = f >> 3, c = (f & 7) * 4;
            float4 q4  = *(const float4*)(g_Q   + baseQ + (size_t)r * H + ck + c);
            float4 qh4 = *(const float4*)(g_QH  + baseQ + (size_t)r * H + ck + c);
            float4 kk4 = *(const float4*)(g_KKH + baseK + (size_t)r * H + ck + c);
            float4 k4  = *(const float4*)(g_K   + baseK + (size_t)r * H + ck + c);
            Qs [r][c+0]=to_tf32(q4.x);  Qs [r][c+1]=to_tf32(q4.y);  Qs [r][c+2]=to_tf32(q4.z);  Qs [r][c+3]=to_tf32(q4.w);
            QHs[r][c+0]=to_tf32(qh4.x); QHs[r][c+1]=to_tf32(qh4.y); QHs[r][c+2]=to_tf32(qh4.z); QHs[r][c+3]=to_tf32(qh4.w);
            KKs[r][c+0]=to_tf32(kk4.x); KKs[r][c+1]=to_tf32(kk4.y); KKs[r][c+2]=to_tf32(kk4.z); KKs[r][c+3]=to_tf32(kk4.w);
            Ks [r][c+0]=to_tf32(k4.x);  Ks [r][c+1]=to_tf32(k4.y);  Ks [r][c+2]=to_tf32(k4.z);  Ks [r][c+3]=to_tf32(k4.w);
        }
        __syncthreads();

        #pragma unroll
        for (int ks = 0; ks < 4; ks++) {
            int k0 = ks * 8;
            uint32_t aq[2][4], ah[2][4];
            #pragma unroll
            for (int mi = 0; mi < 2; mi++) {
                int row = wm + mi * 16 + g;
                aq[mi][0] = __float_as_uint(Qs[row    ][k0 + tg]);
                aq[mi][1] = __float_as_uint(Qs[row + 8][k0 + tg]);
                aq[mi][2] = __float_as_uint(Qs[row    ][k0 + tg + 4]);
                aq[mi][3] = __float_as_uint(Qs[row + 8][k0 + tg + 4]);
                ah[mi][0] = __float_as_uint(QHs[row    ][k0 + tg]);
                ah[mi][1] = __float_as_uint(QHs[row + 8][k0 + tg]);
                ah[mi][2] = __float_as_uint(QHs[row    ][k0 + tg + 4]);
                ah[mi][3] = __float_as_uint(QHs[row + 8][k0 + tg + 4]);
            }
            #pragma unroll
            for (int nj = 0; nj < 8; nj++) {
                int col = wn + nj * 8 + g;
                uint32_t bkk0 = __float_as_uint(KKs[col][k0 + tg]);
                uint32_t bkk1 = __float_as_uint(KKs[col][k0 + tg + 4]);
                uint32_t bk0  = __float_as_uint(Ks [col][k0 + tg]);
                uint32_t bk1  = __float_as_uint(Ks [col][k0 + tg + 4]);
                mma8(acc[0][nj], aq[0], bkk0, bkk1);
                mma8(acc[1][nj], aq[1], bkk0, bkk1);
                mma8(acc[0][nj], ah[0], bk0, bk1);
                mma8(acc[1][nj], ah[1], bk0, bk1);
            }
        }
        __syncthreads();
    }

    float* out = g_SC + ((size_t)bz * S + q0) * S + c0;
    #pragma unroll
    for (int mi = 0; mi < 2; mi++) {
        #pragma unroll
        for (int nj = 0; nj < 8; nj++) {
            int r0  = wm + mi * 16 + g;       // local q row
            int col = wn + nj * 8 + 2 * tg;   // local key col
            #pragma unroll
            for (int half = 0; half < 2; half++) {
                int r = r0 + half * 8;
                float m0v = ((c0 + col)     <= (q0 + r)) ? maskadd[col]     : -10000.0f;
                float m1v = ((c0 + col + 1) <= (q0 + r)) ? maskadd[col + 1] : -10000.0f;
                float v0 = acc[mi][nj][half * 2]     * 0.125f + m0v;
                float v1 = acc[mi][nj][half * 2 + 1] * 0.125f + m1v;
                *(float2*)(out + (size_t)r * S + col) = make_float2(v0, v1);
            }
        }
    }
}

// ---------------- softmax over last dim (512), in place ----------
__global__ __launch_bounds__(256)
void softmax_kernel()
{
    size_t row = blockIdx.x;
    float* p = g_SC + row * S;
    int t = threadIdx.x;
    float v0 = p[t], v1 = p[t + 256];

    __shared__ float red[8];
    __shared__ float bc;

    float m = fmaxf(v0, v1);
    #pragma unroll
    for (int o = 16; o; o >>= 1) m = fmaxf(m, __shfl_xor_sync(0xffffffffu, m, o));
    if ((t & 31) == 0) red[t >> 5] = m;
    __syncthreads();
    if (t == 0) {
        float mm = red[0];
        #pragma unroll
        for (int i = 1; i < 8; i++) mm = fmaxf(mm, red[i]);
        bc = mm;
    }
    __syncthreads();
    m = bc;

    float e0 = expf(v0 - m), e1 = expf(v1 - m);
    float s = e0 + e1;
    #pragma unroll
    for (int o = 16; o; o >>= 1) s += __shfl_xor_sync(0xffffffffu, s, o);
    __syncthreads();
    if ((t & 31) == 0) red[t >> 5] = s;
    __syncthreads();
    if (t == 0) {
        float ss = 0.0f;
        #pragma unroll
        for (int i = 0; i < 8; i++) ss += red[i];
        bc = 1.0f / ss;
    }
    __syncthreads();
    float inv = bc;
    p[t] = e0 * inv;
    p[t + 256] = e1 * inv;
}

// ---------------- ctx = probs @ V via mma.sync ----------------
// grid (S/128, B*NH), 256 threads; warp tile 32q x 32dh
#define PV_SMEM ((128*68 + 64*72) * 4)
__global__ __launch_bounds__(256)
void pv_mma()
{
    extern __shared__ float sm[];
    float (*Ps)[68] = (float(*)[68])(sm);
    float (*Vs)[72] = (float(*)[72])(sm + 128 * 68);

    const int bz = blockIdx.y;
    const int b = bz >> 3;
    const int h = bz & 7;
    const int q0 = blockIdx.x * 128;
    const int tid = threadIdx.x;
    const int lane = tid & 31;
    const int wid = tid >> 5;
    const int wm = (wid & 3) * 32;
    const int wn = (wid >> 2) * 32;
    const int g = lane >> 2;
    const int tg = lane & 3;

    float acc[2][4][4];
    #pragma unroll
    for (int i = 0; i < 2; i++)
        #pragma unroll
        for (int j = 0; j < 4; j++)
            #pragma unroll
            for (int q = 0; q < 4; q++) acc[i][j][q] = 0.0f;

    const float* prob = g_SC + ((size_t)bz * S + q0) * S;

    for (int kk = 0; kk < S; kk += 64) {
        #pragma unroll
        for (int it = 0; it < 8; it++) {
            int f = tid + it * 256;
            int r = f >> 4, c = (f & 15) * 4;
            float4 p4 = *(const float4*)(prob + (size_t)r * S + kk + c);
            Ps[r][c+0]=to_tf32(p4.x); Ps[r][c+1]=to_tf32(p4.y);
            Ps[r][c+2]=to_tf32(p4.z); Ps[r][c+3]=to_tf32(p4.w);
        }
        #pragma unroll
        for (int it = 0; it < 4; it++) {
            int f = tid + it * 256;
            int r = f >> 4, c = (f & 15) * 4;
            float4 v4 = *(const float4*)(g_V + ((size_t)b * S + kk + r) * H + h * DH + c);
            Vs[r][c+0]=to_tf32(v4.x); Vs[r][c+1]=to_tf32(v4.y);
            Vs[r][c+2]=to_tf32(v4.z); Vs[r][c+3]=to_tf32(v4.w);
        }
        __syncthreads();

        #pragma unroll
        for (int ks = 0; ks < 8; ks++) {
            int k0 = ks * 8;
            uint32_t a[2][4];
            #pragma unroll
            for (int mi = 0; mi < 2; mi++) {
                int row = wm + mi * 16 + g;
                a[mi][0] = __float_as_uint(Ps[row    ][k0 + tg]);
                a[mi][1] = __float_as_uint(Ps[row + 8][k0 + tg]);
                a[mi][2] = __float_as_uint(Ps[row    ][k0 + tg + 4]);
                a[mi][3] = __float_as_uint(Ps[row + 8][k0 + tg + 4]);
            }
            #pragma unroll
            for (int nj = 0; nj < 4; nj++) {
                int col = wn + nj * 8 + g;
                uint32_t b0 = __float_as_uint(Vs[k0 + tg    ][col]);
                uint32_t b1 = __float_as_uint(Vs[k0 + tg + 4][col]);
                mma8(acc[0][nj], a[0], b0, b1);
                mma8(acc[1][nj], a[1], b0, b1);
            }
        }
        __syncthreads();
    }

    #pragma unroll
    for (int mi = 0; mi < 2; mi++)
        #pragma unroll
        for (int nj = 0; nj < 4; nj++) {
            int r0  = q0 + wm + mi * 16 + g;
            int col = h * DH + wn + nj * 8 + 2 * tg;
            *(float2*)(g_CTX + ((size_t)b * S + r0) * H + col) =
                make_float2(acc[mi][nj][0], acc[mi][nj][1]);
            *(float2*)(g_CTX + ((size_t)b * S + r0 + 8) * H + col) =
                make_float2(acc[mi][nj][2], acc[mi][nj][3]);
        }
}

// ---------------- LayerNorm over last dim (512) -----------------
__global__ __launch_bounds__(256)
void ln_kernel(const float* __restrict__ in, const float* __restrict__ gam,
               const float* __restrict__ bet, float* __restrict__ out)
{
    size_t row = blockIdx.x;
    const float* p = in + row * H;
    int t = threadIdx.x;
    float x0 = p[t], x1 = p[t + 256];

    __shared__ float r1[8], r2[8];
    float s = x0 + x1;
    float sq = x0 * x0 + x1 * x1;
    #pragma unroll
    for (int o = 16; o; o >>= 1) {
        s  += __shfl_xor_sync(0xffffffffu, s, o);
        sq += __shfl_xor_sync(0xffffffffu, sq, o);
    }
    if ((t & 31) == 0) { r1[t >> 5] = s; r2[t >> 5] = sq; }
    __syncthreads();
    if (t == 0) {
        float S1 = 0.0f, S2 = 0.0f;
        #pragma unroll
        for (int i = 0; i < 8; i++) { S1 += r1[i]; S2 += r2[i]; }
        r1[0] = S1; r2[0] = S2;
    }
    __syncthreads();
    float mean = r1[0] * (1.0f / (float)H);
    float var  = r2[0] * (1.0f / (float)H) - mean * mean;
    float rstd = rsqrtf(var + 1e-12f);
    out[row * H + t]       = (x0 - mean) * rstd * gam[t]       + bet[t];
    out[row * H + t + 256] = (x1 - mean) * rstd * gam[t + 256] + bet[t + 256];
}

// ---------------- launcher ----------------
extern "C" void kernel_launch(void* const* d_in, const int* in_sizes, int n_in,
                              void* d_out, int out_size)
{
    const float* x    = (const float*)d_in[0];
    const float* vin  = (const float*)d_in[1];
    const float* beha = (const float*)d_in[2];
    const float* pos  = (const float*)d_in[3];
    const float* Wq   = (const float*)d_in[4];
    const float* bq   = (const float*)d_in[5];
    const float* Wk   = (const float*)d_in[6];
    const float* bk   = (const float*)d_in[7];
    const float* Wv   = (const float*)d_in[8];
    const float* bv   = (const float*)d_in[9];
    const float* Wpk  = (const float*)d_in[10];
    const float* bpk  = (const float*)d_in[11];
    const float* Wpq  = (const float*)d_in[12];
    const float* bpq  = (const float*)d_in[13];
    const float* Wbk  = (const float*)d_in[14];
    const float* bbk  = (const float*)d_in[15];
    const float* Wbq  = (const float*)d_in[16];
    const float* bbq  = (const float*)d_in[17];
    const float* Wd   = (const float*)d_in[18];
    const float* bd   = (const float*)d_in[19];
    const float* ln_g = (const float*)d_in[20];
    const float* ln_b = (const float*)d_in[21];
    const float* W1   = (const float*)d_in[22];
    const float* b1   = (const float*)d_in[23];
    const float* W2   = (const float*)d_in[24];
    const float* b2   = (const float*)d_in[25];
    const float* ln2g = (const float*)d_in[26];
    const float* ln2b = (const float*)d_in[27];
    const int*   iseq = (const int*)d_in[28];
    float* out = (float*)d_out;

    float *pQ, *pK, *pV, *pKKH, *pQH, *pPK, *pPQ, *pCTX, *pATT, *pAO, *pH1;
    cudaGetSymbolAddress((void**)&pQ,   g_Q);
    cudaGetSymbolAddress((void**)&pK,   g_K);
    cudaGetSymbolAddress((void**)&pV,   g_V);
    cudaGetSymbolAddress((void**)&pKKH, g_KKH);
    cudaGetSymbolAddress((void**)&pQH,  g_QH);
    cudaGetSymbolAddress((void**)&pPK,  g_PK);
    cudaGetSymbolAddress((void**)&pPQ,  g_PQ);
    cudaGetSymbolAddress((void**)&pCTX, g_CTX);
    cudaGetSymbolAddress((void**)&pATT, g_ATT);
    cudaGetSymbolAddress((void**)&pAO,  g_AO);
    cudaGetSymbolAddress((void**)&pH1,  g_H1);

    cudaFuncSetAttribute(scores_mma, cudaFuncAttributeMaxDynamicSharedMemorySize, SC_SMEM);
    cudaFuncSetAttribute(pv_mma,     cudaFuncAttributeMaxDynamicSharedMemorySize, PV_SMEM);

    dim3 blk(256);

    // pos projections: [512,512]
    dim3 gPos(H / 128, S / 128);
    mma_gemm<0><<<gPos, blk>>>(pos, Wpk, bpk, nullptr, pPK, S, H, H);
    mma_gemm<0><<<gPos, blk>>>(pos, Wpq, bpq, nullptr, pPQ, S, H, H);

    // main projections: [16384,512] @ [512,512]
    dim3 gProj(H / 128, BS / 128);
    mma_gemm<0><<<gProj, blk>>>(x,    Wq,  bq,  nullptr, pQ,   BS, H, H);
    mma_gemm<0><<<gProj, blk>>>(x,    Wk,  bk,  nullptr, pK,   BS, H, H);
    mma_gemm<1><<<gProj, blk>>>(vin,  Wv,  bv,  vin,     pV,   BS, H, H);
    mma_gemm<0><<<gProj, blk>>>(beha, Wbk, bbk, nullptr, pKKH, BS, H, H);
    mma_gemm<0><<<gProj, blk>>>(beha, Wbq, bbq, nullptr, pQH,  BS, H, H);

    combine_kernel<<<(BSH / 4) / 256, blk>>>();

    scores_mma<<<dim3(S / 128, S / 128, B * NH), blk, SC_SMEM>>>(iseq);
    softmax_kernel<<<(unsigned)((size_t)B * NH * S), blk>>>();
    pv_mma<<<dim3(S / 128, B * NH), blk, PV_SMEM>>>();

    mma_gemm<1><<<gProj, blk>>>(pCTX, Wd, bd, x, pATT, BS, H, H);
    ln_kernel<<<BS, blk>>>(pATT, ln_g, ln_b, pAO);

    dim3 gF1(INNER / 128, BS / 128);
    mma_gemm<2><<<gF1, blk>>>(pAO, W1, b1, nullptr, pH1, BS, INNER, H);
    dim3 gF2(H / 128, BS / 128);
    mma_gemm<1><<<gF2, blk>>>(pH1, W2, b2, pAO, pATT, BS, H, INNER);
    ln_kernel<<<BS, blk>>>(pATT, ln2g, ln2b, out);
}

// round 4
// speedup vs baseline: 3.3765x; 1.2633x over previous
#include <cuda_runtime.h>
#include <math.h>
#include <stdint.h>

// ---------------- problem constants ----------------
#define B 32
#define S 512
#define H 512
#define NH 8
#define DH 64
#define INNER 2048
#define BS (B*S)            // 16384
#define BSH ((size_t)B*S*H) // 8388608

// ---------------- scratch ----------------
__device__ float g_X  [BSH];   // tf32-rounded copies of inputs
__device__ float g_VIN[BSH];
__device__ float g_BEH[BSH];
__device__ float g_POS[S*H];
__device__ float g_Q  [BSH];
__device__ float g_K  [BSH];
__device__ float g_V  [BSH];
__device__ float g_KKH[BSH];
__device__ float g_QH [BSH];
__device__ float g_PK [S*H];
__device__ float g_PQ [S*H];
__device__ float g_SC [(size_t)B*NH*S*S];
__device__ float g_CTX[BSH];
__device__ float g_ATT[BSH];
__device__ float g_AO [BSH];
__device__ float g_H1 [(size_t)BS*INNER];
__device__ float g_WT [4194304];   // tf32-rounded weights pool

#define WT_Q  0
#define WT_K  262144
#define WT_V  524288
#define WT_BK 786432
#define WT_BQ 1048576
#define WT_D  1310720
#define WT_1  1572864
#define WT_2  2621440
#define WT_PK 3670016
#define WT_PQ 3932160

// ---------------- helpers ----------------
__device__ __forceinline__ uint32_t smem_u32(const void* p) {
    uint32_t a;
    asm("{ .reg .u64 t; cvta.to.shared.u64 t, %1; cvt.u32.u64 %0, t; }"
        : "=r"(a) : "l"(p));
    return a;
}

__device__ __forceinline__ float to_tf32(float x) {
    float r;
    asm("cvt.rna.tf32.f32 %0, %1;" : "=f"(r) : "f"(x));
    return r;
}

__device__ __forceinline__ void mma8(float* c, const uint32_t* a, uint32_t b0, uint32_t b1) {
    asm volatile(
        "mma.sync.aligned.m16n8k8.row.col.f32.tf32.tf32.f32 "
        "{%0,%1,%2,%3}, {%4,%5,%6,%7}, {%8,%9}, {%0,%1,%2,%3};"
        : "+f"(c[0]), "+f"(c[1]), "+f"(c[2]), "+f"(c[3])
        : "r"(a[0]), "r"(a[1]), "r"(a[2]), "r"(a[3]), "r"(b0), "r"(b1));
}

__device__ __forceinline__ void cpa16(uint32_t saddr, const void* gaddr) {
    asm volatile("cp.async.cg.shared.global [%0], [%1], 16;" :: "r"(saddr), "l"(gaddr));
}
#define CP_COMMIT() asm volatile("cp.async.commit_group;" ::: "memory")
#define CP_WAIT(n)  asm volatile("cp.async.wait_group %0;" :: "n"(n) : "memory")

// ================= converters =================
__global__ void cvt4(const float* __restrict__ in, float* __restrict__ out, int n4)
{
    int i = blockIdx.x * blockDim.x + threadIdx.x;
    if (i < n4) {
        float4 v = ((const float4*)in)[i];
        v.x = to_tf32(v.x); v.y = to_tf32(v.y);
        v.z = to_tf32(v.z); v.w = to_tf32(v.w);
        ((float4*)out)[i] = v;
    }
}

// 8 segments of 65536 float4 each
__global__ void cvt8(const float* p0, const float* p1, const float* p2, const float* p3,
                     const float* p4, const float* p5, const float* p6, const float* p7,
                     float* q0, float* q1, float* q2, float* q3,
                     float* q4, float* q5, float* q6, float* q7)
{
    int i = blockIdx.x * blockDim.x + threadIdx.x;
    const float* p; float* q;
    switch (blockIdx.y) {
        case 0: p = p0; q = q0; break;
        case 1: p = p1; q = q1; break;
        case 2: p = p2; q = q2; break;
        case 3: p = p3; q = q3; break;
        case 4: p = p4; q = q4; break;
        case 5: p = p5; q = q5; break;
        case 6: p = p6; q = q6; break;
        default: p = p7; q = q7; break;
    }
    float4 v = ((const float4*)p)[i];
    v.x = to_tf32(v.x); v.y = to_tf32(v.y);
    v.z = to_tf32(v.z); v.w = to_tf32(v.w);
    ((float4*)q)[i] = v;
}

// ================= mma.sync tf32 GEMM, cp.async 3-stage =================
// C[M,N] = A[M,K] @ W[K,N] + bias; EPI: 0 bias, 1 +residual, 2 gelu
// A,W must be tf32-pre-rounded. TF32OUT: round C for GEMM consumers.
#define STG_FLOATS 8960                 // A 128*36 + B 32*136
#define GEMM_SMEM_V2 (3*STG_FLOATS*4)   // 107520 bytes

__device__ __forceinline__ void gemm_issue(uint32_t sstage,
                                           const float* __restrict__ A,
                                           const float* __restrict__ W,
                                           int m0, int n0, int K, int N, int c, int tid)
{
    const float* Ag = A + (size_t)m0 * K + c * 32;
    const float* Wg = W + (size_t)(c * 32) * N + n0;
    #pragma unroll
    for (int i = 0; i < 4; i++) {
        int f = tid + i * 256;
        int r = f >> 3, kq = (f & 7) * 4;
        cpa16(sstage + (uint32_t)(r * 36 + kq) * 4, Ag + (size_t)r * K + kq);
    }
    #pragma unroll
    for (int i = 0; i < 4; i++) {
        int f = tid + i * 256;
        int kr = f >> 5, nq = (f & 31) * 4;
        cpa16(sstage + (uint32_t)(4608 + kr * 136 + nq) * 4, Wg + (size_t)kr * N + nq);
    }
}

template<int EPI, int TF32OUT>
__global__ void __launch_bounds__(256, 2)
mma_gemm(const float* __restrict__ A, const float* __restrict__ W,
         const float* __restrict__ bias, const float* __restrict__ Rres,
         float* __restrict__ C, int M, int N, int K)
{
    extern __shared__ __align__(16) float sm[];
    const uint32_t sbase = smem_u32(sm);
    const int tid  = threadIdx.x;
    const int lane = tid & 31;
    const int wid  = tid >> 5;
    const int wm   = (wid & 3) * 32;
    const int wn   = (wid >> 2) * 64;
    const int m0 = blockIdx.y * 128;
    const int n0 = blockIdx.x * 128;
    const int g  = lane >> 2;
    const int tg = lane & 3;

    float acc[2][8][4];
    #pragma unroll
    for (int i = 0; i < 2; i++)
        #pragma unroll
        for (int j = 0; j < 8; j++)
            #pragma unroll
            for (int q = 0; q < 4; q++) acc[i][j][q] = 0.0f;

    const int NC = K >> 5;
    gemm_issue(sbase,                  A, W, m0, n0, K, N, 0, tid); CP_COMMIT();
    gemm_issue(sbase + STG_FLOATS * 4, A, W, m0, n0, K, N, 1, tid); CP_COMMIT();

    for (int c = 0; c < NC; c++) {
        CP_WAIT(1);
        __syncthreads();
        if (c + 2 < NC) {
            int st = c + 2; st -= (st >= 3) ? 3 : 0; st -= (st >= 3) ? 3 : 0;
            gemm_issue(sbase + (uint32_t)((c + 2) % 3) * (STG_FLOATS * 4),
                       A, W, m0, n0, K, N, c + 2, tid);
        }
        CP_COMMIT();

        float (*As)[36]  = (float(*)[36]) (sm + (c % 3) * STG_FLOATS);
        float (*Bs)[136] = (float(*)[136])(sm + (c % 3) * STG_FLOATS + 4608);
        #pragma unroll
        for (int ks = 0; ks < 4; ks++) {
            int k0 = ks * 8;
            uint32_t a[2][4];
            #pragma unroll
            for (int mi = 0; mi < 2; mi++) {
                int row = wm + mi * 16 + g;
                a[mi][0] = __float_as_uint(As[row    ][k0 + tg]);
                a[mi][1] = __float_as_uint(As[row + 8][k0 + tg]);
                a[mi][2] = __float_as_uint(As[row    ][k0 + tg + 4]);
                a[mi][3] = __float_as_uint(As[row + 8][k0 + tg + 4]);
            }
            #pragma unroll
            for (int nj = 0; nj < 8; nj++) {
                int col = wn + nj * 8 + g;
                uint32_t b0 = __float_as_uint(Bs[k0 + tg    ][col]);
                uint32_t b1 = __float_as_uint(Bs[k0 + tg + 4][col]);
                mma8(acc[0][nj], a[0], b0, b1);
                mma8(acc[1][nj], a[1], b0, b1);
            }
        }
    }

    // epilogue
    #pragma unroll
    for (int mi = 0; mi < 2; mi++) {
        #pragma unroll
        for (int nj = 0; nj < 8; nj++) {
            int r0  = m0 + wm + mi * 16 + g;
            int col = n0 + wn + nj * 8 + 2 * tg;
            float b0 = bias[col], b1 = bias[col + 1];
            float v00 = acc[mi][nj][0] + b0, v01 = acc[mi][nj][1] + b1;
            float v10 = acc[mi][nj][2] + b0, v11 = acc[mi][nj][3] + b1;
            if (EPI == 1) {
                v00 += Rres[(size_t)r0 * N + col];
                v01 += Rres[(size_t)r0 * N + col + 1];
                v10 += Rres[(size_t)(r0 + 8) * N + col];
                v11 += Rres[(size_t)(r0 + 8) * N + col + 1];
            }
            if (EPI == 2) {
                v00 = 0.5f * v00 * (1.0f + erff(v00 * 0.7071067811865475f));
                v01 = 0.5f * v01 * (1.0f + erff(v01 * 0.7071067811865475f));
                v10 = 0.5f * v10 * (1.0f + erff(v10 * 0.7071067811865475f));
                v11 = 0.5f * v11 * (1.0f + erff(v11 * 0.7071067811865475f));
            }
            if (TF32OUT) {
                v00 = to_tf32(v00); v01 = to_tf32(v01);
                v10 = to_tf32(v10); v11 = to_tf32(v11);
            }
            *(float2*)(C + (size_t)r0 * N + col)       = make_float2(v00, v01);
            *(float2*)(C + (size_t)(r0 + 8) * N + col) = make_float2(v10, v11);
        }
    }
}

// ---------------- elementwise combine (emits tf32) ----------------
__global__ void combine_kernel()
{
    int i = blockIdx.x * blockDim.x + threadIdx.x;
    int col4 = i & 127;
    int s = (i >> 7) & 511;
    float4 kk = ((const float4*)g_K)[i];
    float4 kh = ((const float4*)g_KKH)[i];
    float4 pk = ((const float4*)g_PK)[s * 128 + col4];
    float4 qh = ((const float4*)g_QH)[i];
    float4 pq = ((const float4*)g_PQ)[s * 128 + col4];
    float4 o1, o2;
    o1.x = to_tf32(kk.x + 0.5f * (kh.x + pk.x));
    o1.y = to_tf32(kk.y + 0.5f * (kh.y + pk.y));
    o1.z = to_tf32(kk.z + 0.5f * (kh.z + pk.z));
    o1.w = to_tf32(kk.w + 0.5f * (kh.w + pk.w));
    o2.x = to_tf32(0.5f * (qh.x + pq.x));
    o2.y = to_tf32(0.5f * (qh.y + pq.y));
    o2.z = to_tf32(0.5f * (qh.z + pq.z));
    o2.w = to_tf32(0.5f * (qh.w + pq.w));
    ((float4*)g_KKH)[i] = o1;
    ((float4*)g_QH)[i]  = o2;
}

// ---------------- scores: (Q·KKH^T + QH·K^T)/8 + mask ------------
// whole DH=64 loaded once via cp.async; inputs pre-rounded tf32
#define SC_SMEM ((4*128*68 + 128) * 4)
__global__ __launch_bounds__(256)
void scores_mma(const int* __restrict__ iseq)
{
    extern __shared__ __align__(16) float sm[];
    const uint32_t sbase = smem_u32(sm);
    float (*Qs )[68] = (float(*)[68])(sm);
    float (*QHs)[68] = (float(*)[68])(sm + 8704);
    float (*KKs)[68] = (float(*)[68])(sm + 17408);
    float (*Ks )[68] = (float(*)[68])(sm + 26112);
    float* maskadd   = sm + 34816;

    const int bz = blockIdx.z;
    const int b = bz >> 3;
    const int h = bz & 7;
    const int q0 = blockIdx.y * 128;
    const int c0 = blockIdx.x * 128;
    const int tid = threadIdx.x;
    const int lane = tid & 31;
    const int wid = tid >> 5;
    const int wm = (wid & 3) * 32;
    const int wn = (wid >> 2) * 64;
    const int g = lane >> 2;
    const int tg = lane & 3;

    const size_t baseQ = ((size_t)b * S + q0) * H + h * DH;
    const size_t baseK = ((size_t)b * S + c0) * H + h * DH;

    // issue all loads: per tensor 128 rows x 16 f4 = 2048 f4 -> 8 per thread
    #pragma unroll
    for (int i = 0; i < 8; i++) {
        int f = tid + i * 256;
        int r = f >> 4, cq = (f & 15) * 4;
        uint32_t so = (uint32_t)(r * 68 + cq) * 4;
        size_t go = (size_t)r * H + cq;
        cpa16(sbase + so,                 g_Q   + baseQ + go);
        cpa16(sbase + 8704 * 4 + so,      g_QH  + baseQ + go);
        cpa16(sbase + 17408 * 4 + so,     g_KKH + baseK + go);
        cpa16(sbase + 26112 * 4 + so,     g_K   + baseK + go);
    }
    CP_COMMIT();

    if (tid < 128)
        maskadd[tid] = (iseq[b * S + c0 + tid] > 0) ? 0.0f : -10000.0f;

    float acc[2][8][4];
    #pragma unroll
    for (int i = 0; i < 2; i++)
        #pragma unroll
        for (int j = 0; j < 8; j++)
            #pragma unroll
            for (int q = 0; q < 4; q++) acc[i][j][q] = 0.0f;

    CP_WAIT(0);
    __syncthreads();

    #pragma unroll
    for (int ks = 0; ks < 8; ks++) {
        int k0 = ks * 8;
        uint32_t aq[2][4], ah[2][4];
        #pragma unroll
        for (int mi = 0; mi < 2; mi++) {
            int row = wm + mi * 16 + g;
            aq[mi][0] = __float_as_uint(Qs[row    ][k0 + tg]);
            aq[mi][1] = __float_as_uint(Qs[row + 8][k0 + tg]);
            aq[mi][2] = __float_as_uint(Qs[row    ][k0 + tg + 4]);
            aq[mi][3] = __float_as_uint(Qs[row + 8][k0 + tg + 4]);
            ah[mi][0] = __float_as_uint(QHs[row    ][k0 + tg]);
            ah[mi][1] = __float_as_uint(QHs[row + 8][k0 + tg]);
            ah[mi][2] = __float_as_uint(QHs[row    ][k0 + tg + 4]);
            ah[mi][3] = __float_as_uint(QHs[row + 8][k0 + tg + 4]);
        }
        #pragma unroll
        for (int nj = 0; nj < 8; nj++) {
            int col = wn + nj * 8 + g;
            uint32_t bkk0 = __float_as_uint(KKs[col][k0 + tg]);
            uint32_t bkk1 = __float_as_uint(KKs[col][k0 + tg + 4]);
            uint32_t bk0  = __float_as_uint(Ks [col][k0 + tg]);
            uint32_t bk1  = __float_as_uint(Ks [col][k0 + tg + 4]);
            mma8(acc[0][nj], aq[0], bkk0, bkk1);
            mma8(acc[1][nj], aq[1], bkk0, bkk1);
            mma8(acc[0][nj], ah[0], bk0, bk1);
            mma8(acc[1][nj], ah[1], bk0, bk1);
        }
    }

    float* out = g_SC + ((size_t)bz * S + q0) * S + c0;
    #pragma unroll
    for (int mi = 0; mi < 2; mi++) {
        #pragma unroll
        for (int nj = 0; nj < 8; nj++) {
            int r0  = wm + mi * 16 + g;
            int col = wn + nj * 8 + 2 * tg;
            #pragma unroll
            for (int half = 0; half < 2; half++) {
                int r = r0 + half * 8;
                float m0v = ((c0 + col)     <= (q0 + r)) ? maskadd[col]     : -10000.0f;
                float m1v = ((c0 + col + 1) <= (q0 + r)) ? maskadd[col + 1] : -10000.0f;
                float v0 = acc[mi][nj][half * 2]     * 0.125f + m0v;
                float v1 = acc[mi][nj][half * 2 + 1] * 0.125f + m1v;
                *(float2*)(out + (size_t)r * S + col) = make_float2(v0, v1);
            }
        }
    }
}

// ---------------- softmax (emits tf32 probs) ----------
__global__ __launch_bounds__(256)
void softmax_kernel()
{
    size_t row = blockIdx.x;
    float* p = g_SC + row * S;
    int t = threadIdx.x;
    float v0 = p[t], v1 = p[t + 256];

    __shared__ float red[8];
    __shared__ float bc;

    float m = fmaxf(v0, v1);
    #pragma unroll
    for (int o = 16; o; o >>= 1) m = fmaxf(m, __shfl_xor_sync(0xffffffffu, m, o));
    if ((t & 31) == 0) red[t >> 5] = m;
    __syncthreads();
    if (t == 0) {
        float mm = red[0];
        #pragma unroll
        for (int i = 1; i < 8; i++) mm = fmaxf(mm, red[i]);
        bc = mm;
    }
    __syncthreads();
    m = bc;

    float e0 = expf(v0 - m), e1 = expf(v1 - m);
    float s = e0 + e1;
    #pragma unroll
    for (int o = 16; o; o >>= 1) s += __shfl_xor_sync(0xffffffffu, s, o);
    __syncthreads();
    if ((t & 31) == 0) red[t >> 5] = s;
    __syncthreads();
    if (t == 0) {
        float ss = 0.0f;
        #pragma unroll
        for (int i = 0; i < 8; i++) ss += red[i];
        bc = 1.0f / ss;
    }
    __syncthreads();
    float inv = bc;
    p[t]       = to_tf32(e0 * inv);
    p[t + 256] = to_tf32(e1 * inv);
}

// ---------------- ctx = probs @ V, cp.async 2-stage ----------------
#define PV_STG (128*68 + 64*72)        // 13312 floats
#define PV_SMEM (2*PV_STG*4)           // 106496 bytes

__device__ __forceinline__ void pv_issue(uint32_t sstage, const float* __restrict__ prob,
                                         const float* __restrict__ Vbase, int kk, int tid)
{
    // Ps: 128 rows x 16 f4
    #pragma unroll
    for (int i = 0; i < 8; i++) {
        int f = tid + i * 256;
        int r = f >> 4, cq = (f & 15) * 4;
        cpa16(sstage + (uint32_t)(r * 68 + cq) * 4, prob + (size_t)r * S + kk + cq);
    }
    // Vs: 64 rows x 16 f4
    #pragma unroll
    for (int i = 0; i < 4; i++) {
        int f = tid + i * 256;
        int r = f >> 4, cq = (f & 15) * 4;
        cpa16(sstage + (uint32_t)(8704 + r * 72 + cq) * 4,
              Vbase + (size_t)(kk + r) * H + cq);
    }
}

__global__ void __launch_bounds__(256, 2)
pv_mma()
{
    extern __shared__ __align__(16) float sm[];
    const uint32_t sbase = smem_u32(sm);

    const int bz = blockIdx.y;
    const int b = bz >> 3;
    const int h = bz & 7;
    const int q0 = blockIdx.x * 128;
    const int tid = threadIdx.x;
    const int lane = tid & 31;
    const int wid = tid >> 5;
    const int wm = (wid & 3) * 32;
    const int wn = (wid >> 2) * 32;
    const int g = lane >> 2;
    const int tg = lane & 3;

    const float* prob  = g_SC + ((size_t)bz * S + q0) * S;
    const float* Vbase = g_V + (size_t)b * S * H + h * DH;

    float acc[2][4][4];
    #pragma unroll
    for (int i = 0; i < 2; i++)
        #pragma unroll
        for (int j = 0; j < 4; j++)
            #pragma unroll
            for (int q = 0; q < 4; q++) acc[i][j][q] = 0.0f;

    pv_issue(sbase, prob, Vbase, 0, tid); CP_COMMIT();

    for (int c = 0; c < 8; c++) {
        CP_WAIT(0);
        __syncthreads();
        if (c + 1 < 8)
            pv_issue(sbase + (uint32_t)((c + 1) & 1) * (PV_STG * 4), prob, Vbase,
                     (c + 1) * 64, tid);
        CP_COMMIT();

        float (*Ps)[68] = (float(*)[68])(sm + (c & 1) * PV_STG);
        float (*Vs)[72] = (float(*)[72])(sm + (c & 1) * PV_STG + 8704);

        #pragma unroll
        for (int ks = 0; ks < 8; ks++) {
            int k0 = ks * 8;
            uint32_t a[2][4];
            #pragma unroll
            for (int mi = 0; mi < 2; mi++) {
                int row = wm + mi * 16 + g;
                a[mi][0] = __float_as_uint(Ps[row    ][k0 + tg]);
                a[mi][1] = __float_as_uint(Ps[row + 8][k0 + tg]);
                a[mi][2] = __float_as_uint(Ps[row    ][k0 + tg + 4]);
                a[mi][3] = __float_as_uint(Ps[row + 8][k0 + tg + 4]);
            }
            #pragma unroll
            for (int nj = 0; nj < 4; nj++) {
                int col = wn + nj * 8 + g;
                uint32_t b0 = __float_as_uint(Vs[k0 + tg    ][col]);
                uint32_t b1 = __float_as_uint(Vs[k0 + tg + 4][col]);
                mma8(acc[0][nj], a[0], b0, b1);
                mma8(acc[1][nj], a[1], b0, b1);
            }
        }
    }

    #pragma unroll
    for (int mi = 0; mi < 2; mi++)
        #pragma unroll
        for (int nj = 0; nj < 4; nj++) {
            int r0  = q0 + wm + mi * 16 + g;
            int col = h * DH + wn + nj * 8 + 2 * tg;
            *(float2*)(g_CTX + ((size_t)b * S + r0) * H + col) =
                make_float2(to_tf32(acc[mi][nj][0]), to_tf32(acc[mi][nj][1]));
            *(float2*)(g_CTX + ((size_t)b * S + r0 + 8) * H + col) =
                make_float2(to_tf32(acc[mi][nj][2]), to_tf32(acc[mi][nj][3]));
        }
}

// ---------------- LayerNorm (optionally emits tf32) -----------------
template<int ROUND>
__global__ __launch_bounds__(256)
void ln_kernel(const float* __restrict__ in, const float* __restrict__ gam,
               const float* __restrict__ bet, float* __restrict__ out)
{
    size_t row = blockIdx.x;
    const float* p = in + row * H;
    int t = threadIdx.x;
    float x0 = p[t], x1 = p[t + 256];

    __shared__ float r1[8], r2[8];
    float s = x0 + x1;
    float sq = x0 * x0 + x1 * x1;
    #pragma unroll
    for (int o = 16; o; o >>= 1) {
        s  += __shfl_xor_sync(0xffffffffu, s, o);
        sq += __shfl_xor_sync(0xffffffffu, sq, o);
    }
    if ((t & 31) == 0) { r1[t >> 5] = s; r2[t >> 5] = sq; }
    __syncthreads();
    if (t == 0) {
        float S1 = 0.0f, S2 = 0.0f;
        #pragma unroll
        for (int i = 0; i < 8; i++) { S1 += r1[i]; S2 += r2[i]; }
        r1[0] = S1; r2[0] = S2;
    }
    __syncthreads();
    float mean = r1[0] * (1.0f / (float)H);
    float var  = r2[0] * (1.0f / (float)H) - mean * mean;
    float rstd = rsqrtf(var + 1e-12f);
    float o0 = (x0 - mean) * rstd * gam[t]       + bet[t];
    float o1 = (x1 - mean) * rstd * gam[t + 256] + bet[t + 256];
    if (ROUND) { o0 = to_tf32(o0); o1 = to_tf32(o1); }
    out[row * H + t]       = o0;
    out[row * H + t + 256] = o1;
}

// ---------------- launcher ----------------
extern "C" void kernel_launch(void* const* d_in, const int* in_sizes, int n_in,
                              void* d_out, int out_size)
{
    const float* x    = (const float*)d_in[0];
    const float* vin  = (const float*)d_in[1];
    const float* beha = (const float*)d_in[2];
    const float* pos  = (const float*)d_in[3];
    const float* Wq   = (const float*)d_in[4];
    const float* bq   = (const float*)d_in[5];
    const float* Wk   = (const float*)d_in[6];
    const float* bk   = (const float*)d_in[7];
    const float* Wv   = (const float*)d_in[8];
    const float* bv   = (const float*)d_in[9];
    const float* Wpk  = (const float*)d_in[10];
    const float* bpk  = (const float*)d_in[11];
    const float* Wpq  = (const float*)d_in[12];
    const float* bpq  = (const float*)d_in[13];
    const float* Wbk  = (const float*)d_in[14];
    const float* bbk  = (const float*)d_in[15];
    const float* Wbq  = (const float*)d_in[16];
    const float* bbq  = (const float*)d_in[17];
    const float* Wd   = (const float*)d_in[18];
    const float* bd   = (const float*)d_in[19];
    const float* ln_g = (const float*)d_in[20];
    const float* ln_b = (const float*)d_in[21];
    const float* W1   = (const float*)d_in[22];
    const float* b1   = (const float*)d_in[23];
    const float* W2   = (const float*)d_in[24];
    const float* b2   = (const float*)d_in[25];
    const float* ln2g = (const float*)d_in[26];
    const float* ln2b = (const float*)d_in[27];
    const int*   iseq = (const int*)d_in[28];
    float* out = (float*)d_out;

    float *pX, *pVin, *pBeh, *pPos;
    float *pQ, *pK, *pV, *pKKH, *pQH, *pPK, *pPQ, *pCTX, *pATT, *pAO, *pH1, *pWT;
    cudaGetSymbolAddress((void**)&pX,   g_X);
    cudaGetSymbolAddress((void**)&pVin, g_VIN);
    cudaGetSymbolAddress((void**)&pBeh, g_BEH);
    cudaGetSymbolAddress((void**)&pPos, g_POS);
    cudaGetSymbolAddress((void**)&pQ,   g_Q);
    cudaGetSymbolAddress((void**)&pK,   g_K);
    cudaGetSymbolAddress((void**)&pV,   g_V);
    cudaGetSymbolAddress((void**)&pKKH, g_KKH);
    cudaGetSymbolAddress((void**)&pQH,  g_QH);
    cudaGetSymbolAddress((void**)&pPK,  g_PK);
    cudaGetSymbolAddress((void**)&pPQ,  g_PQ);
    cudaGetSymbolAddress((void**)&pCTX, g_CTX);
    cudaGetSymbolAddress((void**)&pATT, g_ATT);
    cudaGetSymbolAddress((void**)&pAO,  g_AO);
    cudaGetSymbolAddress((void**)&pH1,  g_H1);
    cudaGetSymbolAddress((void**)&pWT,  g_WT);

    cudaFuncSetAttribute(mma_gemm<0,0>, cudaFuncAttributeMaxDynamicSharedMemorySize, GEMM_SMEM_V2);
    cudaFuncSetAttribute(mma_gemm<0,1>, cudaFuncAttributeMaxDynamicSharedMemorySize, GEMM_SMEM_V2);
    cudaFuncSetAttribute(mma_gemm<1,0>, cudaFuncAttributeMaxDynamicSharedMemorySize, GEMM_SMEM_V2);
    cudaFuncSetAttribute(mma_gemm<1,1>, cudaFuncAttributeMaxDynamicSharedMemorySize, GEMM_SMEM_V2);
    cudaFuncSetAttribute(mma_gemm<2,1>, cudaFuncAttributeMaxDynamicSharedMemorySize, GEMM_SMEM_V2);
    cudaFuncSetAttribute(scores_mma, cudaFuncAttributeMaxDynamicSharedMemorySize, SC_SMEM);
    cudaFuncSetAttribute(pv_mma,     cudaFuncAttributeMaxDynamicSharedMemorySize, PV_SMEM);

    dim3 blk(256);

    // ---- tf32 pre-conversion ----
    cvt4<<<BSH / 4 / 256, blk>>>(x,    pX,   BSH / 4);
    cvt4<<<BSH / 4 / 256, blk>>>(vin,  pVin, BSH / 4);
    cvt4<<<BSH / 4 / 256, blk>>>(beha, pBeh, BSH / 4);
    cvt4<<<(S * H / 4 + 255) / 256, blk>>>(pos, pPos, S * H / 4);
    cvt8<<<dim3(256, 8), blk>>>(Wq, Wk, Wv, Wbk, Wbq, Wd, Wpk, Wpq,
                                pWT + WT_Q, pWT + WT_K, pWT + WT_V, pWT + WT_BK,
                                pWT + WT_BQ, pWT + WT_D, pWT + WT_PK, pWT + WT_PQ);
    cvt8<<<dim3(256, 8), blk>>>(W1, W1 + 262144, W1 + 524288, W1 + 786432,
                                W2, W2 + 262144, W2 + 524288, W2 + 786432,
                                pWT + WT_1, pWT + WT_1 + 262144, pWT + WT_1 + 524288, pWT + WT_1 + 786432,
                                pWT + WT_2, pWT + WT_2 + 262144, pWT + WT_2 + 524288, pWT + WT_2 + 786432);

    // pos projections
    dim3 gPos(H / 128, S / 128);
    mma_gemm<0,0><<<gPos, blk, GEMM_SMEM_V2>>>(pPos, pWT + WT_PK, bpk, nullptr, pPK, S, H, H);
    mma_gemm<0,0><<<gPos, blk, GEMM_SMEM_V2>>>(pPos, pWT + WT_PQ, bpq, nullptr, pPQ, S, H, H);

    // main projections
    dim3 gProj(H / 128, BS / 128);
    mma_gemm<0,1><<<gProj, blk, GEMM_SMEM_V2>>>(pX,   pWT + WT_Q,  bq,  nullptr, pQ,   BS, H, H);
    mma_gemm<0,1><<<gProj, blk, GEMM_SMEM_V2>>>(pX,   pWT + WT_K,  bk,  nullptr, pK,   BS, H, H);
    mma_gemm<1,1><<<gProj, blk, GEMM_SMEM_V2>>>(pVin, pWT + WT_V,  bv,  vin,     pV,   BS, H, H);
    mma_gemm<0,0><<<gProj, blk, GEMM_SMEM_V2>>>(pBeh, pWT + WT_BK, bbk, nullptr, pKKH, BS, H, H);
    mma_gemm<0,0><<<gProj, blk, GEMM_SMEM_V2>>>(pBeh, pWT + WT_BQ, bbq, nullptr, pQH,  BS, H, H);

    combine_kernel<<<(BSH / 4) / 256, blk>>>();

    scores_mma<<<dim3(S / 128, S / 128, B * NH), blk, SC_SMEM>>>(iseq);
    softmax_kernel<<<(unsigned)((size_t)B * NH * S), blk>>>();
    pv_mma<<<dim3(S / 128, B * NH), blk, PV_SMEM>>>();

    mma_gemm<1,0><<<gProj, blk, GEMM_SMEM_V2>>>(pCTX, pWT + WT_D, bd, x, pATT, BS, H, H);
    ln_kernel<1><<<BS, blk>>>(pATT, ln_g, ln_b, pAO);

    dim3 gF1(INNER / 128, BS / 128);
    mma_gemm<2,1><<<gF1, blk, GEMM_SMEM_V2>>>(pAO, pWT + WT_1, b1, nullptr, pH1, BS, INNER, H);
    dim3 gF2(H / 128, BS / 128);
    mma_gemm<1,0><<<gF2, blk, GEMM_SMEM_V2>>>(pH1, pWT + WT_2, b2, pAO, pATT, BS, H, INNER);
    ln_kernel<0><<<BS, blk>>>(pATT, ln2g, ln2b, out);
}

// round 5
// speedup vs baseline: 4.0572x; 1.2016x over previous
#include <cuda_runtime.h>
#include <math.h>
#include <stdint.h>

// ---------------- problem constants ----------------
#define B 32
#define S 512
#define H 512
#define NH 8
#define DH 64
#define INNER 2048
#define BS (B*S)            // 16384
#define BSH ((size_t)B*S*H) // 8388608

// ---------------- scratch ----------------
__device__ float g_X  [BSH];   // tf32-rounded copies of inputs
__device__ float g_VIN[BSH];
__device__ float g_BEH[BSH];
__device__ float g_POS[S*H];
__device__ float g_Q  [BSH];
__device__ float g_K  [BSH];
__device__ float g_V  [BSH];
__device__ float g_KKH[BSH];
__device__ float g_QH [BSH];
__device__ float g_PK [S*H];
__device__ float g_PQ [S*H];
__device__ float g_CTX[BSH];
__device__ float g_ATT[BSH];
__device__ float g_AO [BSH];
__device__ float g_H1 [(size_t)BS*INNER];
__device__ float g_WT [4194304];   // tf32-rounded weights pool

#define WT_Q  0
#define WT_K  262144
#define WT_V  524288
#define WT_BK 786432
#define WT_BQ 1048576
#define WT_D  1310720
#define WT_1  1572864
#define WT_2  2621440
#define WT_PK 3670016
#define WT_PQ 3932160

// ---------------- helpers ----------------
__device__ __forceinline__ uint32_t smem_u32(const void* p) {
    uint32_t a;
    asm("{ .reg .u64 t; cvta.to.shared.u64 t, %1; cvt.u32.u64 %0, t; }"
        : "=r"(a) : "l"(p));
    return a;
}

__device__ __forceinline__ float to_tf32(float x) {
    float r;
    asm("cvt.rna.tf32.f32 %0, %1;" : "=f"(r) : "f"(x));
    return r;
}

__device__ __forceinline__ void mma8(float* c, const uint32_t* a, uint32_t b0, uint32_t b1) {
    asm volatile(
        "mma.sync.aligned.m16n8k8.row.col.f32.tf32.tf32.f32 "
        "{%0,%1,%2,%3}, {%4,%5,%6,%7}, {%8,%9}, {%0,%1,%2,%3};"
        : "+f"(c[0]), "+f"(c[1]), "+f"(c[2]), "+f"(c[3])
        : "r"(a[0]), "r"(a[1]), "r"(a[2]), "r"(a[3]), "r"(b0), "r"(b1));
}

__device__ __forceinline__ void cpa16(uint32_t saddr, const void* gaddr) {
    asm volatile("cp.async.cg.shared.global [%0], [%1], 16;" :: "r"(saddr), "l"(gaddr));
}
#define CP_COMMIT() asm volatile("cp.async.commit_group;" ::: "memory")
#define CP_WAIT(n)  asm volatile("cp.async.wait_group %0;" :: "n"(n) : "memory")

// ================= converters =================
__global__ void cvt4(const float* __restrict__ in, float* __restrict__ out, int n4)
{
    int i = blockIdx.x * blockDim.x + threadIdx.x;
    if (i < n4) {
        float4 v = ((const float4*)in)[i];
        v.x = to_tf32(v.x); v.y = to_tf32(v.y);
        v.z = to_tf32(v.z); v.w = to_tf32(v.w);
        ((float4*)out)[i] = v;
    }
}

__global__ void cvt8(const float* p0, const float* p1, const float* p2, const float* p3,
                     const float* p4, const float* p5, const float* p6, const float* p7,
                     float* q0, float* q1, float* q2, float* q3,
                     float* q4, float* q5, float* q6, float* q7)
{
    int i = blockIdx.x * blockDim.x + threadIdx.x;
    const float* p; float* q;
    switch (blockIdx.y) {
        case 0: p = p0; q = q0; break;
        case 1: p = p1; q = q1; break;
        case 2: p = p2; q = q2; break;
        case 3: p = p3; q = q3; break;
        case 4: p = p4; q = q4; break;
        case 5: p = p5; q = q5; break;
        case 6: p = p6; q = q6; break;
        default: p = p7; q = q7; break;
    }
    float4 v = ((const float4*)p)[i];
    v.x = to_tf32(v.x); v.y = to_tf32(v.y);
    v.z = to_tf32(v.z); v.w = to_tf32(v.w);
    ((float4*)q)[i] = v;
}

// ================= mma.sync tf32 GEMM, cp.async 3-stage =================
#define STG_FLOATS 8960                 // A 128*36 + B 32*136
#define GEMM_SMEM_V2 (3*STG_FLOATS*4)   // 107520 bytes

__device__ __forceinline__ void gemm_issue(uint32_t sstage,
                                           const float* __restrict__ A,
                                           const float* __restrict__ W,
                                           int m0, int n0, int K, int N, int c, int tid)
{
    const float* Ag = A + (size_t)m0 * K + c * 32;
    const float* Wg = W + (size_t)(c * 32) * N + n0;
    #pragma unroll
    for (int i = 0; i < 4; i++) {
        int f = tid + i * 256;
        int r = f >> 3, kq = (f & 7) * 4;
        cpa16(sstage + (uint32_t)(r * 36 + kq) * 4, Ag + (size_t)r * K + kq);
    }
    #pragma unroll
    for (int i = 0; i < 4; i++) {
        int f = tid + i * 256;
        int kr = f >> 5, nq = (f & 31) * 4;
        cpa16(sstage + (uint32_t)(4608 + kr * 136 + nq) * 4, Wg + (size_t)kr * N + nq);
    }
}

template<int EPI, int TF32OUT>
__global__ void __launch_bounds__(256, 2)
mma_gemm(const float* __restrict__ A, const float* __restrict__ W,
         const float* __restrict__ bias, const float* __restrict__ Rres,
         float* __restrict__ C, int M, int N, int K)
{
    extern __shared__ __align__(16) float sm[];
    const uint32_t sbase = smem_u32(sm);
    const int tid  = threadIdx.x;
    const int lane = tid & 31;
    const int wid  = tid >> 5;
    const int wm   = (wid & 3) * 32;
    const int wn   = (wid >> 2) * 64;
    const int m0 = blockIdx.y * 128;
    const int n0 = blockIdx.x * 128;
    const int g  = lane >> 2;
    const int tg = lane & 3;

    float acc[2][8][4];
    #pragma unroll
    for (int i = 0; i < 2; i++)
        #pragma unroll
        for (int j = 0; j < 8; j++)
            #pragma unroll
            for (int q = 0; q < 4; q++) acc[i][j][q] = 0.0f;

    const int NC = K >> 5;
    gemm_issue(sbase,                  A, W, m0, n0, K, N, 0, tid); CP_COMMIT();
    gemm_issue(sbase + STG_FLOATS * 4, A, W, m0, n0, K, N, 1, tid); CP_COMMIT();

    for (int c = 0; c < NC; c++) {
        CP_WAIT(1);
        __syncthreads();
        if (c + 2 < NC)
            gemm_issue(sbase + (uint32_t)((c + 2) % 3) * (STG_FLOATS * 4),
                       A, W, m0, n0, K, N, c + 2, tid);
        CP_COMMIT();

        float (*As)[36]  = (float(*)[36]) (sm + (c % 3) * STG_FLOATS);
        float (*Bs)[136] = (float(*)[136])(sm + (c % 3) * STG_FLOATS + 4608);
        #pragma unroll
        for (int ks = 0; ks < 4; ks++) {
            int k0 = ks * 8;
            uint32_t a[2][4];
            #pragma unroll
            for (int mi = 0; mi < 2; mi++) {
                int row = wm + mi * 16 + g;
                a[mi][0] = __float_as_uint(As[row    ][k0 + tg]);
                a[mi][1] = __float_as_uint(As[row + 8][k0 + tg]);
                a[mi][2] = __float_as_uint(As[row    ][k0 + tg + 4]);
                a[mi][3] = __float_as_uint(As[row + 8][k0 + tg + 4]);
            }
            #pragma unroll
            for (int nj = 0; nj < 8; nj++) {
                int col = wn + nj * 8 + g;
                uint32_t b0 = __float_as_uint(Bs[k0 + tg    ][col]);
                uint32_t b1 = __float_as_uint(Bs[k0 + tg + 4][col]);
                mma8(acc[0][nj], a[0], b0, b1);
                mma8(acc[1][nj], a[1], b0, b1);
            }
        }
    }

    #pragma unroll
    for (int mi = 0; mi < 2; mi++) {
        #pragma unroll
        for (int nj = 0; nj < 8; nj++) {
            int r0  = m0 + wm + mi * 16 + g;
            int col = n0 + wn + nj * 8 + 2 * tg;
            float b0 = bias[col], b1 = bias[col + 1];
            float v00 = acc[mi][nj][0] + b0, v01 = acc[mi][nj][1] + b1;
            float v10 = acc[mi][nj][2] + b0, v11 = acc[mi][nj][3] + b1;
            if (EPI == 1) {
                v00 += Rres[(size_t)r0 * N + col];
                v01 += Rres[(size_t)r0 * N + col + 1];
                v10 += Rres[(size_t)(r0 + 8) * N + col];
                v11 += Rres[(size_t)(r0 + 8) * N + col + 1];
            }
            if (EPI == 2) {
                v00 = 0.5f * v00 * (1.0f + erff(v00 * 0.7071067811865475f));
                v01 = 0.5f * v01 * (1.0f + erff(v01 * 0.7071067811865475f));
                v10 = 0.5f * v10 * (1.0f + erff(v10 * 0.7071067811865475f));
                v11 = 0.5f * v11 * (1.0f + erff(v11 * 0.7071067811865475f));
            }
            if (TF32OUT) {
                v00 = to_tf32(v00); v01 = to_tf32(v01);
                v10 = to_tf32(v10); v11 = to_tf32(v11);
            }
            *(float2*)(C + (size_t)r0 * N + col)       = make_float2(v00, v01);
            *(float2*)(C + (size_t)(r0 + 8) * N + col) = make_float2(v10, v11);
        }
    }
}

// ---------------- elementwise combine (emits tf32) ----------------
__global__ void combine_kernel()
{
    int i = blockIdx.x * blockDim.x + threadIdx.x;
    int col4 = i & 127;
    int s = (i >> 7) & 511;
    float4 kk = ((const float4*)g_K)[i];
    float4 kh = ((const float4*)g_KKH)[i];
    float4 pk = ((const float4*)g_PK)[s * 128 + col4];
    float4 qh = ((const float4*)g_QH)[i];
    float4 pq = ((const float4*)g_PQ)[s * 128 + col4];
    float4 o1, o2;
    o1.x = to_tf32(kk.x + 0.5f * (kh.x + pk.x));
    o1.y = to_tf32(kk.y + 0.5f * (kh.y + pk.y));
    o1.z = to_tf32(kk.z + 0.5f * (kh.z + pk.z));
    o1.w = to_tf32(kk.w + 0.5f * (kh.w + pk.w));
    o2.x = to_tf32(0.5f * (qh.x + pq.x));
    o2.y = to_tf32(0.5f * (qh.y + pq.y));
    o2.z = to_tf32(0.5f * (qh.z + pq.z));
    o2.w = to_tf32(0.5f * (qh.w + pq.w));
    ((float4*)g_KKH)[i] = o1;
    ((float4*)g_QH)[i]  = o2;
}

// ================= fused flash attention =================
// grid (4 qtiles, B*NH), 256 thr. qtile=128, ktile=64.
// warp w owns q rows [w*16, w*16+16) -> softmax fully warp-local.
#define FL_STAGE 13376   // Kt 64*68 + KKt 64*68 + Vs 64*72 + 64 mask
#define FL_PS_OFF (2*FL_STAGE)
#define FL_SMEM ((2*FL_STAGE + 128*68) * 4)   // 141824 bytes

__device__ __forceinline__ void flash_issue(uint32_t st, int b, int h, int k0,
                                            int tid, const int* __restrict__ iseq)
{
    const float* Kg  = g_K   + ((size_t)(b * S + k0)) * H + h * DH;
    const float* KKg = g_KKH + ((size_t)(b * S + k0)) * H + h * DH;
    const float* Vg  = g_V   + ((size_t)(b * S + k0)) * H + h * DH;
    #pragma unroll
    for (int i = 0; i < 4; i++) {
        int f = tid + i * 256;            // 0..1023
        int r = f >> 4, cq = (f & 15) * 4;
        size_t go = (size_t)r * H + cq;
        cpa16(st + (uint32_t)(r * 68 + cq) * 4,          Kg  + go);
        cpa16(st + (uint32_t)(4352 + r * 68 + cq) * 4,   KKg + go);
        cpa16(st + (uint32_t)(8704 + r * 72 + cq) * 4,   Vg  + go);
    }
    if (tid < 16)
        cpa16(st + (13312 + tid * 4) * 4, iseq + b * S + k0 + tid * 4);
}

__global__ void __launch_bounds__(256)
flash_attn(const int* __restrict__ iseq)
{
    extern __shared__ __align__(16) float sm[];
    const uint32_t sbase = smem_u32(sm);

    const int bz = blockIdx.y;
    const int b = bz >> 3;
    const int h = bz & 7;
    const int qt = 3 - blockIdx.x;        // heavy tiles first
    const int q0 = qt * 128;
    const int tid = threadIdx.x;
    const int lane = tid & 31;
    const int wid = tid >> 5;
    const int r0 = wid * 16;              // warp's q-row base (local)
    const int g = lane >> 2;
    const int tg = lane & 3;

    const int n_kt = 2 * qt + 2;

    // ---- Q / QH fragments in registers (reused all ktiles) ----
    uint32_t qf[8][4], qhf[8][4];
    {
        const float* Qp  = g_Q  + ((size_t)(b * S + q0 + r0 + g)) * H + h * DH;
        const float* Qp8 = Qp + 8 * H;
        const float* Hp  = g_QH + ((size_t)(b * S + q0 + r0 + g)) * H + h * DH;
        const float* Hp8 = Hp + 8 * H;
        #pragma unroll
        for (int ks = 0; ks < 8; ks++) {
            int c = ks * 8 + tg;
            qf[ks][0] = __float_as_uint(__ldg(Qp  + c));
            qf[ks][1] = __float_as_uint(__ldg(Qp8 + c));
            qf[ks][2] = __float_as_uint(__ldg(Qp  + c + 4));
            qf[ks][3] = __float_as_uint(__ldg(Qp8 + c + 4));
            qhf[ks][0] = __float_as_uint(__ldg(Hp  + c));
            qhf[ks][1] = __float_as_uint(__ldg(Hp8 + c));
            qhf[ks][2] = __float_as_uint(__ldg(Hp  + c + 4));
            qhf[ks][3] = __float_as_uint(__ldg(Hp8 + c + 4));
        }
    }

    float oacc[8][4];
    #pragma unroll
    for (int i = 0; i < 8; i++)
        #pragma unroll
        for (int q = 0; q < 4; q++) oacc[i][q] = 0.0f;
    float mrow[2] = {-1e30f, -1e30f};
    float lrow[2] = {0.0f, 0.0f};

    flash_issue(sbase, b, h, 0, tid, iseq); CP_COMMIT();

    for (int j = 0; j < n_kt; j++) {
        const int k0 = j * 64;
        const bool causal = (j >= 2 * qt);
        const int stg = j & 1;

        CP_WAIT(0);
        __syncthreads();
        if (j + 1 < n_kt)
            flash_issue(sbase + (uint32_t)((j + 1) & 1) * (FL_STAGE * 4),
                        b, h, (j + 1) * 64, tid, iseq);
        CP_COMMIT();

        float (*Kt )[68] = (float(*)[68])(sm + stg * FL_STAGE);
        float (*KKt)[68] = (float(*)[68])(sm + stg * FL_STAGE + 4352);
        float (*Vs )[72] = (float(*)[72])(sm + stg * FL_STAGE + 8704);
        const int* maskv = (const int*)(sm + stg * FL_STAGE + 13312);

        // ---- scores: sacc = Q·KKH^T + QH·K^T ----
        float sacc[8][4];
        #pragma unroll
        for (int i = 0; i < 8; i++)
            #pragma unroll
            for (int q = 0; q < 4; q++) sacc[i][q] = 0.0f;

        #pragma unroll
        for (int ks = 0; ks < 8; ks++) {
            int kk = ks * 8;
            #pragma unroll
            for (int nj = 0; nj < 8; nj++) {
                int col = nj * 8 + g;
                uint32_t bkk0 = __float_as_uint(KKt[col][kk + tg]);
                uint32_t bkk1 = __float_as_uint(KKt[col][kk + tg + 4]);
                uint32_t bk0  = __float_as_uint(Kt [col][kk + tg]);
                uint32_t bk1  = __float_as_uint(Kt [col][kk + tg + 4]);
                mma8(sacc[nj], qf[ks],  bkk0, bkk1);
                mma8(sacc[nj], qhf[ks], bk0,  bk1);
            }
        }

        // ---- online softmax (warp-local rows) + P into smem ----
        float (*Ps)[68] = (float(*)[68])(sm + FL_PS_OFF);
        #pragma unroll
        for (int h2 = 0; h2 < 2; h2++) {
            int grow = q0 + r0 + g + 8 * h2;
            float sv[16];
            float tmax = -1e30f;
            #pragma unroll
            for (int nj = 0; nj < 8; nj++) {
                #pragma unroll
                for (int cc = 0; cc < 2; cc++) {
                    int c = nj * 8 + 2 * tg + cc;
                    float madd = (!causal || (k0 + c <= grow))
                                 ? ((maskv[c] > 0) ? 0.0f : -10000.0f)
                                 : -10000.0f;
                    float s = sacc[nj][h2 * 2 + cc] * 0.125f + madd;
                    sv[nj * 2 + cc] = s;
                    tmax = fmaxf(tmax, s);
                }
            }
            tmax = fmaxf(tmax, __shfl_xor_sync(0xffffffffu, tmax, 1));
            tmax = fmaxf(tmax, __shfl_xor_sync(0xffffffffu, tmax, 2));
            float mnew = fmaxf(mrow[h2], tmax);
            float scale = expf(mrow[h2] - mnew);
            mrow[h2] = mnew;
            float rs = 0.0f;
            #pragma unroll
            for (int nj = 0; nj < 8; nj++) {
                float p0 = expf(sv[nj * 2]     - mnew);
                float p1 = expf(sv[nj * 2 + 1] - mnew);
                rs += p0 + p1;
                *(float2*)&Ps[r0 + g + 8 * h2][nj * 8 + 2 * tg] =
                    make_float2(to_tf32(p0), to_tf32(p1));
            }
            rs += __shfl_xor_sync(0xffffffffu, rs, 1);
            rs += __shfl_xor_sync(0xffffffffu, rs, 2);
            lrow[h2] = lrow[h2] * scale + rs;
            #pragma unroll
            for (int nd = 0; nd < 8; nd++) {
                oacc[nd][h2 * 2]     *= scale;
                oacc[nd][h2 * 2 + 1] *= scale;
            }
        }
        __syncwarp();

        // ---- O += P @ V ----
        #pragma unroll
        for (int ks = 0; ks < 8; ks++) {
            int kk = ks * 8;
            uint32_t pa[4];
            pa[0] = __float_as_uint(Ps[r0 + g    ][kk + tg]);
            pa[1] = __float_as_uint(Ps[r0 + g + 8][kk + tg]);
            pa[2] = __float_as_uint(Ps[r0 + g    ][kk + tg + 4]);
            pa[3] = __float_as_uint(Ps[r0 + g + 8][kk + tg + 4]);
            #pragma unroll
            for (int nd = 0; nd < 8; nd++) {
                int col = nd * 8 + g;
                uint32_t b0 = __float_as_uint(Vs[kk + tg    ][col]);
                uint32_t b1 = __float_as_uint(Vs[kk + tg + 4][col]);
                mma8(oacc[nd], pa, b0, b1);
            }
        }
    }

    // ---- finalize ----
    float inv0 = 1.0f / lrow[0];
    float inv1 = 1.0f / lrow[1];
    size_t base = ((size_t)(b * S + q0 + r0 + g)) * H + h * DH;
    #pragma unroll
    for (int nd = 0; nd < 8; nd++) {
        int c = nd * 8 + 2 * tg;
        *(float2*)(g_CTX + base + c) =
            make_float2(to_tf32(oacc[nd][0] * inv0), to_tf32(oacc[nd][1] * inv0));
        *(float2*)(g_CTX + base + 8 * H + c) =
            make_float2(to_tf32(oacc[nd][2] * inv1), to_tf32(oacc[nd][3] * inv1));
    }
}

// ---------------- LayerNorm -----------------
template<int ROUND>
__global__ __launch_bounds__(256)
void ln_kernel(const float* __restrict__ in, const float* __restrict__ gam,
               const float* __restrict__ bet, float* __restrict__ out)
{
    size_t row = blockIdx.x;
    const float* p = in + row * H;
    int t = threadIdx.x;
    float x0 = p[t], x1 = p[t + 256];

    __shared__ float r1[8], r2[8];
    float s = x0 + x1;
    float sq = x0 * x0 + x1 * x1;
    #pragma unroll
    for (int o = 16; o; o >>= 1) {
        s  += __shfl_xor_sync(0xffffffffu, s, o);
        sq += __shfl_xor_sync(0xffffffffu, sq, o);
    }
    if ((t & 31) == 0) { r1[t >> 5] = s; r2[t >> 5] = sq; }
    __syncthreads();
    if (t == 0) {
        float S1 = 0.0f, S2 = 0.0f;
        #pragma unroll
        for (int i = 0; i < 8; i++) { S1 += r1[i]; S2 += r2[i]; }
        r1[0] = S1; r2[0] = S2;
    }
    __syncthreads();
    float mean = r1[0] * (1.0f / (float)H);
    float var  = r2[0] * (1.0f / (float)H) - mean * mean;
    float rstd = rsqrtf(var + 1e-12f);
    float o0 = (x0 - mean) * rstd * gam[t]       + bet[t];
    float o1 = (x1 - mean) * rstd * gam[t + 256] + bet[t + 256];
    if (ROUND) { o0 = to_tf32(o0); o1 = to_tf32(o1); }
    out[row * H + t]       = o0;
    out[row * H + t + 256] = o1;
}

// ---------------- launcher ----------------
extern "C" void kernel_launch(void* const* d_in, const int* in_sizes, int n_in,
                              void* d_out, int out_size)
{
    const float* x    = (const float*)d_in[0];
    const float* vin  = (const float*)d_in[1];
    const float* beha = (const float*)d_in[2];
    const float* pos  = (const float*)d_in[3];
    const float* Wq   = (const float*)d_in[4];
    const float* bq   = (const float*)d_in[5];
    const float* Wk   = (const float*)d_in[6];
    const float* bk   = (const float*)d_in[7];
    const float* Wv   = (const float*)d_in[8];
    const float* bv   = (const float*)d_in[9];
    const float* Wpk  = (const float*)d_in[10];
    const float* bpk  = (const float*)d_in[11];
    const float* Wpq  = (const float*)d_in[12];
    const float* bpq  = (const float*)d_in[13];
    const float* Wbk  = (const float*)d_in[14];
    const float* bbk  = (const float*)d_in[15];
    const float* Wbq  = (const float*)d_in[16];
    const float* bbq  = (const float*)d_in[17];
    const float* Wd   = (const float*)d_in[18];
    const float* bd   = (const float*)d_in[19];
    const float* ln_g = (const float*)d_in[20];
    const float* ln_b = (const float*)d_in[21];
    const float* W1   = (const float*)d_in[22];
    const float* b1   = (const float*)d_in[23];
    const float* W2   = (const float*)d_in[24];
    const float* b2   = (const float*)d_in[25];
    const float* ln2g = (const float*)d_in[26];
    const float* ln2b = (const float*)d_in[27];
    const int*   iseq = (const int*)d_in[28];
    float* out = (float*)d_out;

    float *pX, *pVin, *pBeh, *pPos;
    float *pQ, *pK, *pV, *pKKH, *pQH, *pPK, *pPQ, *pCTX, *pATT, *pAO, *pH1, *pWT;
    cudaGetSymbolAddress((void**)&pX,   g_X);
    cudaGetSymbolAddress((void**)&pVin, g_VIN);
    cudaGetSymbolAddress((void**)&pBeh, g_BEH);
    cudaGetSymbolAddress((void**)&pPos, g_POS);
    cudaGetSymbolAddress((void**)&pQ,   g_Q);
    cudaGetSymbolAddress((void**)&pK,   g_K);
    cudaGetSymbolAddress((void**)&pV,   g_V);
    cudaGetSymbolAddress((void**)&pKKH, g_KKH);
    cudaGetSymbolAddress((void**)&pQH,  g_QH);
    cudaGetSymbolAddress((void**)&pPK,  g_PK);
    cudaGetSymbolAddress((void**)&pPQ,  g_PQ);
    cudaGetSymbolAddress((void**)&pCTX, g_CTX);
    cudaGetSymbolAddress((void**)&pATT, g_ATT);
    cudaGetSymbolAddress((void**)&pAO,  g_AO);
    cudaGetSymbolAddress((void**)&pH1,  g_H1);
    cudaGetSymbolAddress((void**)&pWT,  g_WT);

    cudaFuncSetAttribute(mma_gemm<0,0>, cudaFuncAttributeMaxDynamicSharedMemorySize, GEMM_SMEM_V2);
    cudaFuncSetAttribute(mma_gemm<0,1>, cudaFuncAttributeMaxDynamicSharedMemorySize, GEMM_SMEM_V2);
    cudaFuncSetAttribute(mma_gemm<1,0>, cudaFuncAttributeMaxDynamicSharedMemorySize, GEMM_SMEM_V2);
    cudaFuncSetAttribute(mma_gemm<1,1>, cudaFuncAttributeMaxDynamicSharedMemorySize, GEMM_SMEM_V2);
    cudaFuncSetAttribute(mma_gemm<2,1>, cudaFuncAttributeMaxDynamicSharedMemorySize, GEMM_SMEM_V2);
    cudaFuncSetAttribute(flash_attn, cudaFuncAttributeMaxDynamicSharedMemorySize, FL_SMEM);

    dim3 blk(256);

    // ---- tf32 pre-conversion ----
    cvt4<<<BSH / 4 / 256, blk>>>(x,    pX,   BSH / 4);
    cvt4<<<BSH / 4 / 256, blk>>>(vin,  pVin, BSH / 4);
    cvt4<<<BSH / 4 / 256, blk>>>(beha, pBeh, BSH / 4);
    cvt4<<<(S * H / 4 + 255) / 256, blk>>>(pos, pPos, S * H / 4);
    cvt8<<<dim3(256, 8), blk>>>(Wq, Wk, Wv, Wbk, Wbq, Wd, Wpk, Wpq,
                                pWT + WT_Q, pWT + WT_K, pWT + WT_V, pWT + WT_BK,
                                pWT + WT_BQ, pWT + WT_D, pWT + WT_PK, pWT + WT_PQ);
    cvt8<<<dim3(256, 8), blk>>>(W1, W1 + 262144, W1 + 524288, W1 + 786432,
                                W2, W2 + 262144, W2 + 524288, W2 + 786432,
                                pWT + WT_1, pWT + WT_1 + 262144, pWT + WT_1 + 524288, pWT + WT_1 + 786432,
                                pWT + WT_2, pWT + WT_2 + 262144, pWT + WT_2 + 524288, pWT + WT_2 + 786432);

    // pos projections
    dim3 gPos(H / 128, S / 128);
    mma_gemm<0,0><<<gPos, blk, GEMM_SMEM_V2>>>(pPos, pWT + WT_PK, bpk, nullptr, pPK, S, H, H);
    mma_gemm<0,0><<<gPos, blk, GEMM_SMEM_V2>>>(pPos, pWT + WT_PQ, bpq, nullptr, pPQ, S, H, H);

    // main projections
    dim3 gProj(H / 128, BS / 128);
    mma_gemm<0,1><<<gProj, blk, GEMM_SMEM_V2>>>(pX,   pWT + WT_Q,  bq,  nullptr, pQ,   BS, H, H);
    mma_gemm<0,1><<<gProj, blk, GEMM_SMEM_V2>>>(pX,   pWT + WT_K,  bk,  nullptr, pK,   BS, H, H);
    mma_gemm<1,1><<<gProj, blk, GEMM_SMEM_V2>>>(pVin, pWT + WT_V,  bv,  vin,     pV,   BS, H, H);
    mma_gemm<0,0><<<gProj, blk, GEMM_SMEM_V2>>>(pBeh, pWT + WT_BK, bbk, nullptr, pKKH, BS, H, H);
    mma_gemm<0,0><<<gProj, blk, GEMM_SMEM_V2>>>(pBeh, pWT + WT_BQ, bbq, nullptr, pQH,  BS, H, H);

    combine_kernel<<<(BSH / 4) / 256, blk>>>();

    // fused attention
    flash_attn<<<dim3(S / 128, B * NH), blk, FL_SMEM>>>(iseq);

    mma_gemm<1,0><<<gProj, blk, GEMM_SMEM_V2>>>(pCTX, pWT + WT_D, bd, x, pATT, BS, H, H);
    ln_kernel<1><<<BS, blk>>>(pATT, ln_g, ln_b, pAO);

    dim3 gF1(INNER / 128, BS / 128);
    mma_gemm<2,1><<<gF1, blk, GEMM_SMEM_V2>>>(pAO, pWT + WT_1, b1, nullptr, pH1, BS, INNER, H);
    dim3 gF2(H / 128, BS / 128);
    mma_gemm<1,0><<<gF2, blk, GEMM_SMEM_V2>>>(pH1, pWT + WT_2, b2, pAO, pATT, BS, H, INNER);
    ln_kernel<0><<<BS, blk>>>(pATT, ln2g, ln2b, out);
}

// round 6
// speedup vs baseline: 4.1014x; 1.0109x over previous
#include <cuda_runtime.h>
#include <math.h>
#include <stdint.h>

// ---------------- problem constants ----------------
#define B 32
#define S 512
#define H 512
#define NH 8
#define DH 64
#define INNER 2048
#define BS (B*S)            // 16384
#define BSH ((size_t)B*S*H) // 8388608

// ---------------- scratch ----------------
__device__ float g_X  [BSH];
__device__ float g_VIN[BSH];
__device__ float g_BEH[BSH];
__device__ float g_POS[S*H];
__device__ float g_Q  [BSH];
__device__ float g_K  [BSH];
__device__ float g_V  [BSH];
__device__ float g_KKH[BSH];
__device__ float g_QH [BSH];
__device__ float g_PK [S*H];
__device__ float g_PQ [S*H];
__device__ float g_CTX[BSH];
__device__ float g_ATT[BSH];
__device__ float g_AO [BSH];
__device__ float g_H1 [(size_t)BS*INNER];
__device__ float g_WT [4194304];   // tf32 weights pool
__device__ float g_BQK[1024];      // packed bq|bk
__device__ float g_BB2[1024];      // packed bbk|bbq

// offsets into g_WT (floats)
#define WT_QK   0          // 512x1024 packed Wq|Wk
#define WT_BKBQ 524288     // 512x1024 packed Wbk|Wbq
#define WT_V    1048576
#define WT_D    1310720
#define WT_1    1572864
#define WT_2    2621440
#define WT_PK   3670016
#define WT_PQ   3932160

// ---------------- helpers ----------------
__device__ __forceinline__ uint32_t smem_u32(const void* p) {
    uint32_t a;
    asm("{ .reg .u64 t; cvta.to.shared.u64 t, %1; cvt.u32.u64 %0, t; }"
        : "=r"(a) : "l"(p));
    return a;
}

__device__ __forceinline__ float to_tf32(float x) {
    float r;
    asm("cvt.rna.tf32.f32 %0, %1;" : "=f"(r) : "f"(x));
    return r;
}

__device__ __forceinline__ void mma8(float* c, const uint32_t* a, uint32_t b0, uint32_t b1) {
    asm volatile(
        "mma.sync.aligned.m16n8k8.row.col.f32.tf32.tf32.f32 "
        "{%0,%1,%2,%3}, {%4,%5,%6,%7}, {%8,%9}, {%0,%1,%2,%3};"
        : "+f"(c[0]), "+f"(c[1]), "+f"(c[2]), "+f"(c[3])
        : "r"(a[0]), "r"(a[1]), "r"(a[2]), "r"(a[3]), "r"(b0), "r"(b1));
}

__device__ __forceinline__ void cpa16(uint32_t saddr, const void* gaddr) {
    asm volatile("cp.async.cg.shared.global [%0], [%1], 16;" :: "r"(saddr), "l"(gaddr));
}
#define CP_COMMIT() asm volatile("cp.async.commit_group;" ::: "memory")
#define CP_WAIT(n)  asm volatile("cp.async.wait_group %0;" :: "n"(n) : "memory")

// ================= converters / packers =================
__device__ __forceinline__ float4 rnd4(float4 v) {
    v.x = to_tf32(v.x); v.y = to_tf32(v.y);
    v.z = to_tf32(v.z); v.w = to_tf32(v.w);
    return v;
}

// all big activations in one launch: x, vin, beha (2097152 f4 each), pos (65536 f4)
#define N_ACT (3*2097152 + 65536)
__global__ void cvt_inputs(const float* __restrict__ x, const float* __restrict__ vin,
                           const float* __restrict__ beha, const float* __restrict__ pos)
{
    int i = blockIdx.x * blockDim.x + threadIdx.x;
    if (i >= N_ACT) return;
    const float* p; float* q; int off;
    if (i < 2097152)      { p = x;    q = g_X;   off = i; }
    else if (i < 4194304) { p = vin;  q = g_VIN; off = i - 2097152; }
    else if (i < 6291456) { p = beha; q = g_BEH; off = i - 4194304; }
    else                  { p = pos;  q = g_POS; off = i - 6291456; }
    ((float4*)q)[off] = rnd4(((const float4*)p)[off]);
}

__global__ void cvt4(const float* __restrict__ in, float* __restrict__ out, int n4)
{
    int i = blockIdx.x * blockDim.x + threadIdx.x;
    if (i < n4) ((float4*)out)[i] = rnd4(((const float4*)in)[i]);
}

__global__ void cvt8(const float* p0, const float* p1, const float* p2, const float* p3,
                     const float* p4, const float* p5, const float* p6, const float* p7,
                     float* q0, float* q1, float* q2, float* q3,
                     float* q4, float* q5, float* q6, float* q7)
{
    int i = blockIdx.x * blockDim.x + threadIdx.x;
    const float* p; float* q;
    switch (blockIdx.y) {
        case 0: p = p0; q = q0; break;
        case 1: p = p1; q = q1; break;
        case 2: p = p2; q = q2; break;
        case 3: p = p3; q = q3; break;
        case 4: p = p4; q = q4; break;
        case 5: p = p5; q = q5; break;
        case 6: p = p6; q = q6; break;
        default: p = p7; q = q7; break;
    }
    ((float4*)q)[i] = rnd4(((const float4*)p)[i]);
}

// pack two [512,512] weights into [512,1024] tf32 (+ pack biases into g-arrays)
__global__ void pack2(const float* __restrict__ A1, const float* __restrict__ A2,
                      float* __restrict__ outW,
                      const float* __restrict__ b1, const float* __restrict__ b2,
                      float* __restrict__ outB)
{
    int i = blockIdx.x * blockDim.x + threadIdx.x;   // f4 index, 131072 total
    int row = i >> 8;
    int c4 = i & 255;
    const float* src = (c4 < 128) ? (A1 + (size_t)row * 512 + c4 * 4)
                                  : (A2 + (size_t)row * 512 + (c4 - 128) * 4);
    ((float4*)outW)[i] = rnd4(*(const float4*)src);
    if (i < 256) {
        int c = i * 4;
        const float* sb = (c < 512) ? (b1 + c) : (b2 + c - 512);
        *(float4*)(outB + c) = *(const float4*)sb;
    }
}

// ================= mma.sync tf32 GEMM, cp.async 3-stage =================
// EPI: 0 bias, 1 +residual, 2 gelu, 3 split write (C/C2 halves),
//      4 combine: half0 C=Rres+0.5*(acc+bias+P1), half1 C2=0.5*(acc+bias+P2)
#define STG_FLOATS 8960                 // A 128*36 + B 32*136
#define GEMM_SMEM_V2 (3*STG_FLOATS*4)   // 107520 bytes

__device__ __forceinline__ void gemm_issue(uint32_t sstage,
                                           const float* __restrict__ A,
                                           const float* __restrict__ W,
                                           int m0, int n0, int K, int N, int c, int tid)
{
    const float* Ag = A + (size_t)m0 * K + c * 32;
    const float* Wg = W + (size_t)(c * 32) * N + n0;
    #pragma unroll
    for (int i = 0; i < 4; i++) {
        int f = tid + i * 256;
        int r = f >> 3, kq = (f & 7) * 4;
        cpa16(sstage + (uint32_t)(r * 36 + kq) * 4, Ag + (size_t)r * K + kq);
    }
    #pragma unroll
    for (int i = 0; i < 4; i++) {
        int f = tid + i * 256;
        int kr = f >> 5, nq = (f & 31) * 4;
        cpa16(sstage + (uint32_t)(4608 + kr * 136 + nq) * 4, Wg + (size_t)kr * N + nq);
    }
}

template<int EPI, int TF32OUT>
__global__ void __launch_bounds__(256, 2)
mma_gemm(const float* __restrict__ A, const float* __restrict__ W,
         const float* __restrict__ bias, const float* __restrict__ Rres,
         const float* __restrict__ P1, const float* __restrict__ P2,
         float* __restrict__ C, float* __restrict__ C2,
         int M, int N, int K)
{
    extern __shared__ __align__(16) float sm[];
    const uint32_t sbase = smem_u32(sm);
    const int tid  = threadIdx.x;
    const int lane = tid & 31;
    const int wid  = tid >> 5;
    const int wm   = (wid & 3) * 32;
    const int wn   = (wid >> 2) * 64;
    const int m0 = blockIdx.y * 128;
    const int n0 = blockIdx.x * 128;
    const int g  = lane >> 2;
    const int tg = lane & 3;

    float acc[2][8][4];
    #pragma unroll
    for (int i = 0; i < 2; i++)
        #pragma unroll
        for (int j = 0; j < 8; j++)
            #pragma unroll
            for (int q = 0; q < 4; q++) acc[i][j][q] = 0.0f;

    const int NC = K >> 5;
    gemm_issue(sbase,                  A, W, m0, n0, K, N, 0, tid); CP_COMMIT();
    gemm_issue(sbase + STG_FLOATS * 4, A, W, m0, n0, K, N, 1, tid); CP_COMMIT();

    for (int c = 0; c < NC; c++) {
        CP_WAIT(1);
        __syncthreads();
        if (c + 2 < NC)
            gemm_issue(sbase + (uint32_t)((c + 2) % 3) * (STG_FLOATS * 4),
                       A, W, m0, n0, K, N, c + 2, tid);
        CP_COMMIT();

        float (*As)[36]  = (float(*)[36]) (sm + (c % 3) * STG_FLOATS);
        float (*Bs)[136] = (float(*)[136])(sm + (c % 3) * STG_FLOATS + 4608);
        #pragma unroll
        for (int ks = 0; ks < 4; ks++) {
            int k0 = ks * 8;
            uint32_t a[2][4];
            #pragma unroll
            for (int mi = 0; mi < 2; mi++) {
                int row = wm + mi * 16 + g;
                a[mi][0] = __float_as_uint(As[row    ][k0 + tg]);
                a[mi][1] = __float_as_uint(As[row + 8][k0 + tg]);
                a[mi][2] = __float_as_uint(As[row    ][k0 + tg + 4]);
                a[mi][3] = __float_as_uint(As[row + 8][k0 + tg + 4]);
            }
            #pragma unroll
            for (int nj = 0; nj < 8; nj++) {
                int col = wn + nj * 8 + g;
                uint32_t b0 = __float_as_uint(Bs[k0 + tg    ][col]);
                uint32_t b1 = __float_as_uint(Bs[k0 + tg + 4][col]);
                mma8(acc[0][nj], a[0], b0, b1);
                mma8(acc[1][nj], a[1], b0, b1);
            }
        }
    }

    // epilogue
    #pragma unroll
    for (int mi = 0; mi < 2; mi++) {
        #pragma unroll
        for (int nj = 0; nj < 8; nj++) {
            int r0  = m0 + wm + mi * 16 + g;
            int colG = n0 + wn + nj * 8 + 2 * tg;
            float b0 = bias[colG], b1 = bias[colG + 1];
            float v00 = acc[mi][nj][0] + b0, v01 = acc[mi][nj][1] + b1;
            float v10 = acc[mi][nj][2] + b0, v11 = acc[mi][nj][3] + b1;

            if (EPI == 1) {
                v00 += Rres[(size_t)r0 * N + colG];
                v01 += Rres[(size_t)r0 * N + colG + 1];
                v10 += Rres[(size_t)(r0 + 8) * N + colG];
                v11 += Rres[(size_t)(r0 + 8) * N + colG + 1];
            }
            if (EPI == 2) {
                v00 = 0.5f * v00 * (1.0f + erff(v00 * 0.7071067811865475f));
                v01 = 0.5f * v01 * (1.0f + erff(v01 * 0.7071067811865475f));
                v10 = 0.5f * v10 * (1.0f + erff(v10 * 0.7071067811865475f));
                v11 = 0.5f * v11 * (1.0f + erff(v11 * 0.7071067811865475f));
            }

            if (EPI == 3 || EPI == 4) {
                const bool half = colG >= 512;
                const int coln = colG - (half ? 512 : 0);
                float* Cw = half ? C2 : C;
                if (EPI == 4) {
                    int s0 = r0 & (S - 1);
                    const float* P = half ? P2 : P1;
                    float p00 = P[(size_t)s0 * 512 + coln];
                    float p01 = P[(size_t)s0 * 512 + coln + 1];
                    float p10 = P[(size_t)(s0 + 8) * 512 + coln];
                    float p11 = P[(size_t)(s0 + 8) * 512 + coln + 1];
                    if (!half) {
                        v00 = Rres[(size_t)r0 * 512 + coln]           + 0.5f * (v00 + p00);
                        v01 = Rres[(size_t)r0 * 512 + coln + 1]       + 0.5f * (v01 + p01);
                        v10 = Rres[(size_t)(r0 + 8) * 512 + coln]     + 0.5f * (v10 + p10);
                        v11 = Rres[(size_t)(r0 + 8) * 512 + coln + 1] + 0.5f * (v11 + p11);
                    } else {
                        v00 = 0.5f * (v00 + p00);
                        v01 = 0.5f * (v01 + p01);
                        v10 = 0.5f * (v10 + p10);
                        v11 = 0.5f * (v11 + p11);
                    }
                }
                if (TF32OUT) {
                    v00 = to_tf32(v00); v01 = to_tf32(v01);
                    v10 = to_tf32(v10); v11 = to_tf32(v11);
                }
                *(float2*)(Cw + (size_t)r0 * 512 + coln)       = make_float2(v00, v01);
                *(float2*)(Cw + (size_t)(r0 + 8) * 512 + coln) = make_float2(v10, v11);
            } else {
                if (TF32OUT) {
                    v00 = to_tf32(v00); v01 = to_tf32(v01);
                    v10 = to_tf32(v10); v11 = to_tf32(v11);
                }
                *(float2*)(C + (size_t)r0 * N + colG)       = make_float2(v00, v01);
                *(float2*)(C + (size_t)(r0 + 8) * N + colG) = make_float2(v10, v11);
            }
        }
    }
}

// ================= fused flash attention =================
#define FL_STAGE 13376   // Kt 64*68 + KKt 64*68 + Vs 64*72 + 64 mask
#define FL_PS_OFF (2*FL_STAGE)
#define FL_SMEM ((2*FL_STAGE + 128*68) * 4)   // 141824 bytes

__device__ __forceinline__ void flash_issue(uint32_t st, int b, int h, int k0,
                                            int tid, const int* __restrict__ iseq)
{
    const float* Kg  = g_K   + ((size_t)(b * S + k0)) * H + h * DH;
    const float* KKg = g_KKH + ((size_t)(b * S + k0)) * H + h * DH;
    const float* Vg  = g_V   + ((size_t)(b * S + k0)) * H + h * DH;
    #pragma unroll
    for (int i = 0; i < 4; i++) {
        int f = tid + i * 256;
        int r = f >> 4, cq = (f & 15) * 4;
        size_t go = (size_t)r * H + cq;
        cpa16(st + (uint32_t)(r * 68 + cq) * 4,          Kg  + go);
        cpa16(st + (uint32_t)(4352 + r * 68 + cq) * 4,   KKg + go);
        cpa16(st + (uint32_t)(8704 + r * 72 + cq) * 4,   Vg  + go);
    }
    if (tid < 16)
        cpa16(st + (13312 + tid * 4) * 4, iseq + b * S + k0 + tid * 4);
}

__global__ void __launch_bounds__(256)
flash_attn(const int* __restrict__ iseq)
{
    extern __shared__ __align__(16) float sm[];
    const uint32_t sbase = smem_u32(sm);

    const int bz = blockIdx.y;
    const int b = bz >> 3;
    const int h = bz & 7;
    const int qt = 3 - blockIdx.x;
    const int q0 = qt * 128;
    const int tid = threadIdx.x;
    const int lane = tid & 31;
    const int wid = tid >> 5;
    const int r0 = wid * 16;
    const int g = lane >> 2;
    const int tg = lane & 3;

    const int n_kt = 2 * qt + 2;

    uint32_t qf[8][4], qhf[8][4];
    {
        const float* Qp  = g_Q  + ((size_t)(b * S + q0 + r0 + g)) * H + h * DH;
        const float* Qp8 = Qp + 8 * H;
        const float* Hp  = g_QH + ((size_t)(b * S + q0 + r0 + g)) * H + h * DH;
        const float* Hp8 = Hp + 8 * H;
        #pragma unroll
        for (int ks = 0; ks < 8; ks++) {
            int c = ks * 8 + tg;
            qf[ks][0] = __float_as_uint(__ldg(Qp  + c));
            qf[ks][1] = __float_as_uint(__ldg(Qp8 + c));
            qf[ks][2] = __float_as_uint(__ldg(Qp  + c + 4));
            qf[ks][3] = __float_as_uint(__ldg(Qp8 + c + 4));
            qhf[ks][0] = __float_as_uint(__ldg(Hp  + c));
            qhf[ks][1] = __float_as_uint(__ldg(Hp8 + c));
            qhf[ks][2] = __float_as_uint(__ldg(Hp  + c + 4));
            qhf[ks][3] = __float_as_uint(__ldg(Hp8 + c + 4));
        }
    }

    float oacc[8][4];
    #pragma unroll
    for (int i = 0; i < 8; i++)
        #pragma unroll
        for (int q = 0; q < 4; q++) oacc[i][q] = 0.0f;
    float mrow[2] = {-1e30f, -1e30f};
    float lrow[2] = {0.0f, 0.0f};

    flash_issue(sbase, b, h, 0, tid, iseq); CP_COMMIT();

    for (int j = 0; j < n_kt; j++) {
        const int k0 = j * 64;
        const bool causal = (j >= 2 * qt);
        const int stg = j & 1;

        CP_WAIT(0);
        __syncthreads();
        if (j + 1 < n_kt)
            flash_issue(sbase + (uint32_t)((j + 1) & 1) * (FL_STAGE * 4),
                        b, h, (j + 1) * 64, tid, iseq);
        CP_COMMIT();

        float (*Kt )[68] = (float(*)[68])(sm + stg * FL_STAGE);
        float (*KKt)[68] = (float(*)[68])(sm + stg * FL_STAGE + 4352);
        float (*Vs )[72] = (float(*)[72])(sm + stg * FL_STAGE + 8704);
        const int* maskv = (const int*)(sm + stg * FL_STAGE + 13312);

        float sacc[8][4];
        #pragma unroll
        for (int i = 0; i < 8; i++)
            #pragma unroll
            for (int q = 0; q < 4; q++) sacc[i][q] = 0.0f;

        #pragma unroll
        for (int ks = 0; ks < 8; ks++) {
            int kk = ks * 8;
            #pragma unroll
            for (int nj = 0; nj < 8; nj++) {
                int col = nj * 8 + g;
                uint32_t bkk0 = __float_as_uint(KKt[col][kk + tg]);
                uint32_t bkk1 = __float_as_uint(KKt[col][kk + tg + 4]);
                uint32_t bk0  = __float_as_uint(Kt [col][kk + tg]);
                uint32_t bk1  = __float_as_uint(Kt [col][kk + tg + 4]);
                mma8(sacc[nj], qf[ks],  bkk0, bkk1);
                mma8(sacc[nj], qhf[ks], bk0,  bk1);
            }
        }

        float (*Ps)[68] = (float(*)[68])(sm + FL_PS_OFF);
        #pragma unroll
        for (int h2 = 0; h2 < 2; h2++) {
            int grow = q0 + r0 + g + 8 * h2;
            float sv[16];
            float tmax = -1e30f;
            #pragma unroll
            for (int nj = 0; nj < 8; nj++) {
                #pragma unroll
                for (int cc = 0; cc < 2; cc++) {
                    int c = nj * 8 + 2 * tg + cc;
                    float madd = (!causal || (k0 + c <= grow))
                                 ? ((maskv[c] > 0) ? 0.0f : -10000.0f)
                                 : -10000.0f;
                    float s = sacc[nj][h2 * 2 + cc] * 0.125f + madd;
                    sv[nj * 2 + cc] = s;
                    tmax = fmaxf(tmax, s);
                }
            }
            tmax = fmaxf(tmax, __shfl_xor_sync(0xffffffffu, tmax, 1));
            tmax = fmaxf(tmax, __shfl_xor_sync(0xffffffffu, tmax, 2));
            float mnew = fmaxf(mrow[h2], tmax);
            float scale = expf(mrow[h2] - mnew);
            mrow[h2] = mnew;
            float rs = 0.0f;
            #pragma unroll
            for (int nj = 0; nj < 8; nj++) {
                float p0 = expf(sv[nj * 2]     - mnew);
                float p1 = expf(sv[nj * 2 + 1] - mnew);
                rs += p0 + p1;
                *(float2*)&Ps[r0 + g + 8 * h2][nj * 8 + 2 * tg] =
                    make_float2(to_tf32(p0), to_tf32(p1));
            }
            rs += __shfl_xor_sync(0xffffffffu, rs, 1);
            rs += __shfl_xor_sync(0xffffffffu, rs, 2);
            lrow[h2] = lrow[h2] * scale + rs;
            #pragma unroll
            for (int nd = 0; nd < 8; nd++) {
                oacc[nd][h2 * 2]     *= scale;
                oacc[nd][h2 * 2 + 1] *= scale;
            }
        }
        __syncwarp();

        #pragma unroll
        for (int ks = 0; ks < 8; ks++) {
            int kk = ks * 8;
            uint32_t pa[4];
            pa[0] = __float_as_uint(Ps[r0 + g    ][kk + tg]);
            pa[1] = __float_as_uint(Ps[r0 + g + 8][kk + tg]);
            pa[2] = __float_as_uint(Ps[r0 + g    ][kk + tg + 4]);
            pa[3] = __float_as_uint(Ps[r0 + g + 8][kk + tg + 4]);
            #pragma unroll
            for (int nd = 0; nd < 8; nd++) {
                int col = nd * 8 + g;
                uint32_t b0 = __float_as_uint(Vs[kk + tg    ][col]);
                uint32_t b1 = __float_as_uint(Vs[kk + tg + 4][col]);
                mma8(oacc[nd], pa, b0, b1);
            }
        }
    }

    float inv0 = 1.0f / lrow[0];
    float inv1 = 1.0f / lrow[1];
    size_t base = ((size_t)(b * S + q0 + r0 + g)) * H + h * DH;
    #pragma unroll
    for (int nd = 0; nd < 8; nd++) {
        int c = nd * 8 + 2 * tg;
        *(float2*)(g_CTX + base + c) =
            make_float2(to_tf32(oacc[nd][0] * inv0), to_tf32(oacc[nd][1] * inv0));
        *(float2*)(g_CTX + base + 8 * H + c) =
            make_float2(to_tf32(oacc[nd][2] * inv1), to_tf32(oacc[nd][3] * inv1));
    }
}

// ---------------- LayerNorm -----------------
template<int ROUND>
__global__ __launch_bounds__(256)
void ln_kernel(const float* __restrict__ in, const float* __restrict__ gam,
               const float* __restrict__ bet, float* __restrict__ out)
{
    size_t row = blockIdx.x;
    const float* p = in + row * H;
    int t = threadIdx.x;
    float x0 = p[t], x1 = p[t + 256];

    __shared__ float r1[8], r2[8];
    float s = x0 + x1;
    float sq = x0 * x0 + x1 * x1;
    #pragma unroll
    for (int o = 16; o; o >>= 1) {
        s  += __shfl_xor_sync(0xffffffffu, s, o);
        sq += __shfl_xor_sync(0xffffffffu, sq, o);
    }
    if ((t & 31) == 0) { r1[t >> 5] = s; r2[t >> 5] = sq; }
    __syncthreads();
    if (t == 0) {
        float S1 = 0.0f, S2 = 0.0f;
        #pragma unroll
        for (int i = 0; i < 8; i++) { S1 += r1[i]; S2 += r2[i]; }
        r1[0] = S1; r2[0] = S2;
    }
    __syncthreads();
    float mean = r1[0] * (1.0f / (float)H);
    float var  = r2[0] * (1.0f / (float)H) - mean * mean;
    float rstd = rsqrtf(var + 1e-12f);
    float o0 = (x0 - mean) * rstd * gam[t]       + bet[t];
    float o1 = (x1 - mean) * rstd * gam[t + 256] + bet[t + 256];
    if (ROUND) { o0 = to_tf32(o0); o1 = to_tf32(o1); }
    out[row * H + t]       = o0;
    out[row * H + t + 256] = o1;
}

// ---------------- launcher ----------------
extern "C" void kernel_launch(void* const* d_in, const int* in_sizes, int n_in,
                              void* d_out, int out_size)
{
    const float* x    = (const float*)d_in[0];
    const float* vin  = (const float*)d_in[1];
    const float* beha = (const float*)d_in[2];
    const float* pos  = (const float*)d_in[3];
    const float* Wq   = (const float*)d_in[4];
    const float* bq   = (const float*)d_in[5];
    const float* Wk   = (const float*)d_in[6];
    const float* bk   = (const float*)d_in[7];
    const float* Wv   = (const float*)d_in[8];
    const float* bv   = (const float*)d_in[9];
    const float* Wpk  = (const float*)d_in[10];
    const float* bpk  = (const float*)d_in[11];
    const float* Wpq  = (const float*)d_in[12];
    const float* bpq  = (const float*)d_in[13];
    const float* Wbk  = (const float*)d_in[14];
    const float* bbk  = (const float*)d_in[15];
    const float* Wbq  = (const float*)d_in[16];
    const float* bbq  = (const float*)d_in[17];
    const float* Wd   = (const float*)d_in[18];
    const float* bd   = (const float*)d_in[19];
    const float* ln_g = (const float*)d_in[20];
    const float* ln_b = (const float*)d_in[21];
    const float* W1   = (const float*)d_in[22];
    const float* b1   = (const float*)d_in[23];
    const float* W2   = (const float*)d_in[24];
    const float* b2   = (const float*)d_in[25];
    const float* ln2g = (const float*)d_in[26];
    const float* ln2b = (const float*)d_in[27];
    const int*   iseq = (const int*)d_in[28];
    float* out = (float*)d_out;

    float *pX, *pVin, *pBeh, *pPos;
    float *pQ, *pK, *pV, *pKKH, *pQH, *pPK, *pPQ, *pCTX, *pATT, *pAO, *pH1, *pWT;
    float *pBQK, *pBB2;
    cudaGetSymbolAddress((void**)&pX,   g_X);
    cudaGetSymbolAddress((void**)&pVin, g_VIN);
    cudaGetSymbolAddress((void**)&pBeh, g_BEH);
    cudaGetSymbolAddress((void**)&pPos, g_POS);
    cudaGetSymbolAddress((void**)&pQ,   g_Q);
    cudaGetSymbolAddress((void**)&pK,   g_K);
    cudaGetSymbolAddress((void**)&pV,   g_V);
    cudaGetSymbolAddress((void**)&pKKH, g_KKH);
    cudaGetSymbolAddress((void**)&pQH,  g_QH);
    cudaGetSymbolAddress((void**)&pPK,  g_PK);
    cudaGetSymbolAddress((void**)&pPQ,  g_PQ);
    cudaGetSymbolAddress((void**)&pCTX, g_CTX);
    cudaGetSymbolAddress((void**)&pATT, g_ATT);
    cudaGetSymbolAddress((void**)&pAO,  g_AO);
    cudaGetSymbolAddress((void**)&pH1,  g_H1);
    cudaGetSymbolAddress((void**)&pWT,  g_WT);
    cudaGetSymbolAddress((void**)&pBQK, g_BQK);
    cudaGetSymbolAddress((void**)&pBB2, g_BB2);

    cudaFuncSetAttribute(mma_gemm<0,0>, cudaFuncAttributeMaxDynamicSharedMemorySize, GEMM_SMEM_V2);
    cudaFuncSetAttribute(mma_gemm<1,0>, cudaFuncAttributeMaxDynamicSharedMemorySize, GEMM_SMEM_V2);
    cudaFuncSetAttribute(mma_gemm<1,1>, cudaFuncAttributeMaxDynamicSharedMemorySize, GEMM_SMEM_V2);
    cudaFuncSetAttribute(mma_gemm<2,1>, cudaFuncAttributeMaxDynamicSharedMemorySize, GEMM_SMEM_V2);
    cudaFuncSetAttribute(mma_gemm<3,1>, cudaFuncAttributeMaxDynamicSharedMemorySize, GEMM_SMEM_V2);
    cudaFuncSetAttribute(mma_gemm<4,1>, cudaFuncAttributeMaxDynamicSharedMemorySize, GEMM_SMEM_V2);
    cudaFuncSetAttribute(flash_attn, cudaFuncAttributeMaxDynamicSharedMemorySize, FL_SMEM);

    dim3 blk(256);

    // ---- conversions / packing ----
    cvt_inputs<<<(N_ACT + 255) / 256, blk>>>(x, vin, beha, pos);
    cvt8<<<dim3(256, 8), blk>>>(Wv, Wd, Wpk, Wpq,
                                W1, W1 + 262144, W1 + 524288, W1 + 786432,
                                pWT + WT_V, pWT + WT_D, pWT + WT_PK, pWT + WT_PQ,
                                pWT + WT_1, pWT + WT_1 + 262144, pWT + WT_1 + 524288, pWT + WT_1 + 786432);
    cvt4<<<1024, blk>>>(W2, pWT + WT_2, 262144);
    pack2<<<512, blk>>>(Wq,  Wk,  pWT + WT_QK,   bq,  bk,  pBQK);
    pack2<<<512, blk>>>(Wbk, Wbq, pWT + WT_BKBQ, bbk, bbq, pBB2);

    // pos projections
    dim3 gPos(H / 128, S / 128);
    mma_gemm<0,0><<<gPos, blk, GEMM_SMEM_V2>>>(pPos, pWT + WT_PK, bpk, nullptr, nullptr, nullptr, pPK, nullptr, S, H, H);
    mma_gemm<0,0><<<gPos, blk, GEMM_SMEM_V2>>>(pPos, pWT + WT_PQ, bpq, nullptr, nullptr, nullptr, pPQ, nullptr, S, H, H);

    // fused Q|K projection
    dim3 gQK(1024 / 128, BS / 128);
    mma_gemm<3,1><<<gQK, blk, GEMM_SMEM_V2>>>(pX, pWT + WT_QK, pBQK, nullptr, nullptr, nullptr, pQ, pK, BS, 1024, H);
    // V projection (+residual)
    dim3 gProj(H / 128, BS / 128);
    mma_gemm<1,1><<<gProj, blk, GEMM_SMEM_V2>>>(pVin, pWT + WT_V, bv, vin, nullptr, nullptr, pV, nullptr, BS, H, H);
    // fused BK|BQ projection with combine folded in (needs g_K, g_PK, g_PQ)
    mma_gemm<4,1><<<gQK, blk, GEMM_SMEM_V2>>>(pBeh, pWT + WT_BKBQ, pBB2, pK, pPK, pPQ, pKKH, pQH, BS, 1024, H);

    // fused attention
    flash_attn<<<dim3(S / 128, B * NH), blk, FL_SMEM>>>(iseq);

    mma_gemm<1,0><<<gProj, blk, GEMM_SMEM_V2>>>(pCTX, pWT + WT_D, bd, x, nullptr, nullptr, pATT, nullptr, BS, H, H);
    ln_kernel<1><<<BS, blk>>>(pATT, ln_g, ln_b, pAO);

    dim3 gF1(INNER / 128, BS / 128);
    mma_gemm<2,1><<<gF1, blk, GEMM_SMEM_V2>>>(pAO, pWT + WT_1, b1, nullptr, nullptr, nullptr, pH1, nullptr, BS, INNER, H);
    dim3 gF2(H / 128, BS / 128);
    mma_gemm<1,0><<<gF2, blk, GEMM_SMEM_V2>>>(pH1, pWT + WT_2, b2, pAO, nullptr, nullptr, pATT, nullptr, BS, H, INNER);
    ln_kernel<0><<<BS, blk>>>(pATT, ln2g, ln2b, out);
}